// round 15
// baseline (speedup 1.0000x reference)
#include <cuda_runtime.h>
#include <cuda_bf16.h>
#include <math.h>
#include <stdint.h>

// Problem constants
#define BB 2
#define HH 256
#define WW 256
#define NN 65536          // H*W
#define CC 128
#define HEADS 8
#define DH 64             // dim_head
#define GG 64             // SLICE
#define INNER 512         // HEADS*DH
#define SPLITS 64         // split-K for token reduction
#define CHUNK 1024        // tokens per split (NN/SPLITS)
#define KTOT 1152         // 9 taps * 128 channels

// ---------------- device scratch (static, no allocs) ----------------
__device__ float g_tokp[(size_t)SPLITS * BB * HEADS * GG * DH];
__device__ float g_normp[(size_t)SPLITS * BB * HEADS * GG];
__device__ float g_tok [(size_t)BB * HEADS * GG * DH];
__device__ float g_norm[(size_t)BB * HEADS * GG];
__device__ float g_lbias[INNER];                     // (bx·Wslice + bslice)/temp

// fx_mid as single bf16  [b][n][inner]
__device__ __align__(16) __nv_bfloat16 g_fxhi[(size_t)BB * NN * INNER];
// slice weights as bf16 hi/lo pair  [bh][n][g]
__device__ __align__(16) __nv_bfloat16 g_swhi[(size_t)BB * HEADS * NN * GG];
__device__ __align__(16) __nv_bfloat16 g_swlo[(size_t)BB * HEADS * NN * GG];
// Mt = (out_slice · Wout^T) transposed: [b][o][h*64+g], bf16 hi/lo
__device__ __align__(16) __nv_bfloat16 g_Mthi[(size_t)BB * CC * INNER];
__device__ __align__(16) __nv_bfloat16 g_Mtlo[(size_t)BB * CC * INNER];

// bf16 3-split staging for conv
__device__ __align__(16) __nv_bfloat16 g_xhi[(size_t)BB * NN * CC];
__device__ __align__(16) __nv_bfloat16 g_xlo[(size_t)BB * NN * CC];
// rows 0..511: Wfx cols; rows 512..1023: combined logit weights (Wx·Wslice/temp)
__device__ __align__(16) __nv_bfloat16 g_whi[(size_t)1024 * KTOT];
__device__ __align__(16) __nv_bfloat16 g_wlo[(size_t)1024 * KTOT];

// ---------------- prep kernels ----------------
__global__ void split_x_kernel(const float* __restrict__ x,
                               __nv_bfloat16* __restrict__ xhi,
                               __nv_bfloat16* __restrict__ xlo) {
    size_t i = (size_t)blockIdx.x * 256 + threadIdx.x;
    float f = x[i];
    __nv_bfloat16 h = __float2bfloat16(f);
    float r = f - __bfloat162float(h);
    xhi[i] = h;
    xlo[i] = __float2bfloat16(r);
}

__global__ void split_w_kernel(const float* __restrict__ Wfx,
                               __nv_bfloat16* __restrict__ whi,
                               __nv_bfloat16* __restrict__ wlo) {
    int i = blockIdx.x * 256 + threadIdx.x;   // 512*1152 total
    int oc = i / KTOT;
    int k  = i - oc * KTOT;
    float f = Wfx[(size_t)k * 512 + oc];
    __nv_bfloat16 h = __float2bfloat16(f);
    float r = f - __bfloat162float(h);
    whi[i] = h;
    wlo[i] = __float2bfloat16(r);
}

__global__ void combine_w_kernel(const float* __restrict__ Wx,
                                 const float* __restrict__ Wsl,
                                 const float* __restrict__ bx,
                                 const float* __restrict__ bsl,
                                 const float* __restrict__ temp,
                                 __nv_bfloat16* __restrict__ whi,
                                 __nv_bfloat16* __restrict__ wlo,
                                 float* __restrict__ lb) {
    __shared__ float ws[64];
    const int col = blockIdx.x;          // 0..511
    const int h = col >> 6, g = col & 63;
    const int tid = threadIdx.x;         // 128
    if (tid < 64) ws[tid] = Wsl[g * 64 + tid];
    __syncthreads();
    float t = fminf(fmaxf(temp[h], 0.1f), 5.0f);
    float invt = 1.0f / t;

    if (blockIdx.y == 9) {
        if (tid < 32) {
            float s = bx[h * 64 + tid] * ws[tid]
                    + bx[h * 64 + 32 + tid] * ws[32 + tid];
            #pragma unroll
            for (int o = 16; o > 0; o >>= 1)
                s += __shfl_xor_sync(0xffffffffu, s, o);
            if (tid == 0) lb[col] = (s + bsl[g]) * invt;
        }
        return;
    }

    int k = blockIdx.y * 128 + tid;      // 9 y-blocks -> 0..1151
    const float* wr = Wx + (size_t)k * 512 + h * 64;
    float s = 0.f;
    #pragma unroll 8
    for (int d = 0; d < 64; d++) s += wr[d] * ws[d];
    s *= invt;
    __nv_bfloat16 hv = __float2bfloat16(s);
    size_t o = (size_t)(512 + col) * KTOT + k;
    whi[o] = hv;
    wlo[o] = __float2bfloat16(s - __bfloat162float(hv));
}

// ---------------- shared MMA plumbing ----------------
__device__ __forceinline__ void cp16(uint32_t saddr, const void* g, bool valid) {
    int sz = valid ? 16 : 0;
    asm volatile("cp.async.cg.shared.global [%0], [%1], 16, %2;\n"
                 :: "r"(saddr), "l"(g), "r"(sz));
}

__device__ __forceinline__ void mma_bf16(float c[4], uint32_t a0, uint32_t a1,
                                         uint32_t a2, uint32_t a3,
                                         uint32_t b0, uint32_t b1) {
    asm volatile(
        "mma.sync.aligned.m16n8k16.row.col.f32.bf16.bf16.f32 "
        "{%0,%1,%2,%3}, {%4,%5,%6,%7}, {%8,%9}, {%0,%1,%2,%3};"
        : "+f"(c[0]), "+f"(c[1]), "+f"(c[2]), "+f"(c[3])
        : "r"(a0), "r"(a1), "r"(a2), "r"(a3), "r"(b0), "r"(b1));
}

__device__ __forceinline__ void ldsm4(uint32_t r[4], uint32_t addr) {
    asm volatile("ldmatrix.sync.aligned.m8n8.x4.shared.b16 {%0,%1,%2,%3}, [%4];"
                 : "=r"(r[0]), "=r"(r[1]), "=r"(r[2]), "=r"(r[3]) : "r"(addr));
}

__device__ __forceinline__ void ldsm4t(uint32_t r[4], uint32_t addr) {
    asm volatile("ldmatrix.sync.aligned.m8n8.x4.trans.shared.b16 {%0,%1,%2,%3}, [%4];"
                 : "=r"(r[0]), "=r"(r[1]), "=r"(r[2]), "=r"(r[3]) : "r"(addr));
}

// packed kc=32 tile: 128 logical rows x 32 bf16, two logical rows per 128B phys row.
__device__ __forceinline__ uint32_t sw32(int row, int gr) {
    return (uint32_t)(row >> 1) * 128 +
           (uint32_t)(((gr | ((row & 1) << 2)) ^ ((row >> 1) & 7)) << 4);
}

// ---------------- conv: implicit GEMM 128x128, kc=32, 4 warps, 3 CTAs/SM ----------------
// 2-stage pipeline (64KB) + softmax staging needs 67.6KB -> smem/CTA = 67.6KB.
#define CSTAGE 32768
#define NCHUNK 36
#define CSMEM (128 * 132 * 4)   // 67584 >= 2*CSTAGE

__device__ __forceinline__ void conv_load(
    uint32_t st,
    const __nv_bfloat16* __restrict__ Xhi, const __nv_bfloat16* __restrict__ Xlo,
    const __nv_bfloat16* __restrict__ Whi, const __nv_bfloat16* __restrict__ Wlo,
    int it, int b, int hrow, int w0, int ocb, int tid)
{
    const int kg  = it * 32;
    const int tap = kg >> 7;
    const int dy = tap / 3 - 1, dx = tap % 3 - 1;
    const int c0 = kg & 127;            // 0/32/64/96
    const int hp = hrow + dy;
    const bool hok = (hp >= 0) && (hp < HH);
    const int hpc = hok ? hp : 0;

    #pragma unroll
    for (int j = 0; j < 8; j++) {
        int id  = tid + j * 128;
        int arr = id >> 9;              // 0:Ahi 1:Alo
        int l   = id & 511;
        int row = l >> 2;
        int gr  = l & 3;
        uint32_t saddr = st + arr * 8192 + sw32(row, gr);
        int wp = w0 + row + dx;
        bool valid = hok && (wp >= 0) && (wp < WW);
        int wpc = valid ? wp : 0;
        const __nv_bfloat16* g = (arr == 0 ? Xhi : Xlo) +
            (((size_t)b * NN + (size_t)hpc * WW + wpc) * CC + c0 + gr * 8);
        cp16(saddr, g, valid);
    }
    #pragma unroll
    for (int j = 0; j < 8; j++) {
        int id  = tid + j * 128;
        int arr = id >> 9;              // 0:Bhi 1:Blo
        int l   = id & 511;
        int row = l >> 2;
        int gr  = l & 3;
        uint32_t saddr = st + 16384 + arr * 8192 + sw32(row, gr);
        const __nv_bfloat16* g = (arr == 0 ? Whi : Wlo) +
            ((size_t)(ocb * 128 + row) * KTOT + kg + gr * 8);
        cp16(saddr, g, true);
    }
}

__global__ __launch_bounds__(128, 3)
void conv_mma_kernel(const __nv_bfloat16* __restrict__ Xhi,
                     const __nv_bfloat16* __restrict__ Xlo,
                     const __nv_bfloat16* __restrict__ Whi,
                     const __nv_bfloat16* __restrict__ Wlo,
                     const float* __restrict__ bfx,
                     const float* __restrict__ lbias,
                     __nv_bfloat16* __restrict__ fxhi,
                     __nv_bfloat16* __restrict__ swhi,
                     __nv_bfloat16* __restrict__ swlo)
{
    extern __shared__ char smem[];           // CSMEM (2 stages + softmax staging)

    const int ocb = blockIdx.x;              // 0..7
    const int pt  = blockIdx.y;              // 0..511
    const int b   = blockIdx.z;
    const int n0  = pt * 128;
    const int hrow = n0 >> 8;
    const int w0   = n0 & 255;

    const int tid  = threadIdx.x;            // 0..127
    const int wid  = tid >> 5;               // 0..3
    const int lane = tid & 31;
    const int grp  = lane >> 2;
    const int tid4 = lane & 3;
    const int wm   = wid & 1;                // 2 row-groups of 64
    const int wn   = wid >> 1;               // 2 col-groups of 64

    const int t8   = lane >> 3;
    const int r8   = lane & 7;
    const int a_roff = ((t8 & 1) << 3) + r8;
    const int a_gsel = t8 >> 1;
    const int b_roff = ((t8 >> 1) << 3) + r8;
    const int b_gsel = t8 & 1;

    float acc[4][8][4];
    #pragma unroll
    for (int i = 0; i < 4; i++)
        #pragma unroll
        for (int j = 0; j < 8; j++)
            #pragma unroll
            for (int r = 0; r < 4; r++) acc[i][j][r] = 0.f;

    uint32_t sbase = (uint32_t)__cvta_generic_to_shared(smem);

    conv_load(sbase, Xhi, Xlo, Whi, Wlo, 0, b, hrow, w0, ocb, tid);
    asm volatile("cp.async.commit_group;\n" ::: "memory");

    for (int it = 0; it < NCHUNK; ++it) {
        const int cur = it & 1;
        if (it + 1 < NCHUNK) {
            conv_load(sbase + (uint32_t)(1 - cur) * CSTAGE,
                      Xhi, Xlo, Whi, Wlo, it + 1, b, hrow, w0, ocb, tid);
            asm volatile("cp.async.commit_group;\n" ::: "memory");
            asm volatile("cp.async.wait_group 1;\n" ::: "memory");
        } else {
            asm volatile("cp.async.wait_group 0;\n" ::: "memory");
        }
        __syncthreads();

        const uint32_t stA = sbase + (uint32_t)cur * CSTAGE;
        const uint32_t stB = stA + 16384;

        #pragma unroll
        for (int s = 0; s < 2; s++) {
            uint32_t ah[4][4], al[4][4];
            #pragma unroll
            for (int mi = 0; mi < 4; mi++) {
                int row = wm * 64 + mi * 16 + a_roff;
                int g = 2 * s + a_gsel;
                uint32_t addr = stA + sw32(row, g);
                ldsm4(ah[mi], addr);
                ldsm4(al[mi], addr + 8192);
            }
            #pragma unroll
            for (int np = 0; np < 4; np++) {
                int row = wn * 64 + np * 16 + b_roff;
                int g = 2 * s + b_gsel;
                uint32_t addr = stB + sw32(row, g);
                uint32_t bh[4], bl[4];
                ldsm4(bh, addr);
                ldsm4(bl, addr + 8192);
                #pragma unroll
                for (int mi = 0; mi < 4; mi++) {
                    mma_bf16(acc[mi][2 * np],     ah[mi][0], ah[mi][1], ah[mi][2], ah[mi][3], bh[0], bh[1]);
                    mma_bf16(acc[mi][2 * np + 1], ah[mi][0], ah[mi][1], ah[mi][2], ah[mi][3], bh[2], bh[3]);
                }
                #pragma unroll
                for (int mi = 0; mi < 4; mi++) {
                    mma_bf16(acc[mi][2 * np],     ah[mi][0], ah[mi][1], ah[mi][2], ah[mi][3], bl[0], bl[1]);
                    mma_bf16(acc[mi][2 * np + 1], ah[mi][0], ah[mi][1], ah[mi][2], ah[mi][3], bl[2], bl[3]);
                }
                #pragma unroll
                for (int mi = 0; mi < 4; mi++) {
                    mma_bf16(acc[mi][2 * np],     al[mi][0], al[mi][1], al[mi][2], al[mi][3], bh[0], bh[1]);
                    mma_bf16(acc[mi][2 * np + 1], al[mi][0], al[mi][1], al[mi][2], al[mi][3], bh[2], bh[3]);
                }
            }
        }
        __syncthreads();
    }

    if (ocb < 4) {
        const int ocbase = ocb * 128;
        #pragma unroll
        for (int mi = 0; mi < 4; mi++) {
            int row = wm * 64 + mi * 16 + grp;
            int n  = n0 + row;
            #pragma unroll
            for (int ni = 0; ni < 8; ni++) {
                int col = wn * 64 + ni * 8 + tid4 * 2;
                int oc  = ocbase + col;
                float b0v = bfx[oc], b1v = bfx[oc + 1];
                __nv_bfloat162 p0;
                p0.x = __float2bfloat16(acc[mi][ni][0] + b0v);
                p0.y = __float2bfloat16(acc[mi][ni][1] + b1v);
                __nv_bfloat162 p1;
                p1.x = __float2bfloat16(acc[mi][ni][2] + b0v);
                p1.y = __float2bfloat16(acc[mi][ni][3] + b1v);
                *(__nv_bfloat162*)(fxhi + ((size_t)b * NN + n) * INNER + oc) = p0;
                *(__nv_bfloat162*)(fxhi + ((size_t)b * NN + n + 8) * INNER + oc) = p1;
            }
        }
    } else {
        float* sred = (float*)smem;          // [128][132] = 67.5KB
        #pragma unroll
        for (int mi = 0; mi < 4; mi++) {
            int row = wm * 64 + mi * 16 + grp;
            #pragma unroll
            for (int ni = 0; ni < 8; ni++) {
                int col = wn * 64 + ni * 8 + tid4 * 2;
                sred[row * 132 + col]           = acc[mi][ni][0];
                sred[row * 132 + col + 1]       = acc[mi][ni][1];
                sred[(row + 8) * 132 + col]     = acc[mi][ni][2];
                sred[(row + 8) * 132 + col + 1] = acc[mi][ni][3];
            }
        }
        __syncthreads();

        #pragma unroll
        for (int pass = 0; pass < 2; pass++) {
            int tsk = tid + pass * 128;      // 0..255
            int row  = tsk >> 1;
            int hloc = tsk & 1;
            int h = (ocb - 4) * 2 + hloc;
            int n = n0 + row;
            const float* lb = lbias + h * 64;
            float* sr = sred + row * 132 + hloc * 64;

            float mx = -1e30f;
            #pragma unroll 8
            for (int g = 0; g < 64; g++) mx = fmaxf(mx, sr[g] + lb[g]);
            float ssum = 0.f;
            #pragma unroll 8
            for (int g = 0; g < 64; g++) {
                float e = __expf(sr[g] + lb[g] - mx);
                ssum += e;
                sr[g] = e;
            }
            float inv = 1.0f / ssum;

            size_t base = ((size_t)(b * HEADS + h) * NN + n) * GG;
            #pragma unroll
            for (int c = 0; c < 8; c++) {
                union { __nv_bfloat16 hb[8]; uint4 u; } Uh, Ul;
                #pragma unroll
                for (int e = 0; e < 8; e++) {
                    float v = sr[c * 8 + e] * inv;
                    __nv_bfloat16 hv = __float2bfloat16(v);
                    Uh.hb[e] = hv;
                    Ul.hb[e] = __float2bfloat16(v - __bfloat162float(hv));
                }
                ((uint4*)(swhi + base))[c] = Uh.u;
                ((uint4*)(swlo + base))[c] = Ul.u;
            }
        }
    }
}

// ---------------- K3: token reduction on tensor cores (fx single bf16) ----------------
__global__ __launch_bounds__(128)
void token_mma_kernel(const __nv_bfloat16* __restrict__ whi,
                      const __nv_bfloat16* __restrict__ wlo,
                      const __nv_bfloat16* __restrict__ fx,
                      float* __restrict__ tokp,
                      float* __restrict__ normp)
{
    __shared__ __align__(16) char smem[2 * 6144];

    const int bh = blockIdx.y;
    const int b = bh >> 3, h = bh & 7;
    const int split = blockIdx.x;
    const int nbase = split * CHUNK;

    const int tid  = threadIdx.x;
    const int wid  = tid >> 5;          // 0..3: g-strip wid*16
    const int lane = tid & 31;
    const int grp  = lane >> 2;
    const int tid4 = lane & 3;
    const int t8   = lane >> 3;
    const int r8   = lane & 7;
    const int lrow = r8 + ((t8 >> 1) << 3);   // 0..15
    const int lgr  = t8 & 1;

    const uint32_t ONES = 0x3F803F80u;  // bf16(1.0) x2

    float acc[8][4];
    #pragma unroll
    for (int j = 0; j < 8; j++)
        #pragma unroll
        for (int r = 0; r < 4; r++) acc[j][r] = 0.f;
    float accn[4] = {};

    uint32_t sbase = (uint32_t)__cvta_generic_to_shared(smem);

    auto load = [&](uint32_t st, int t0) {
        #pragma unroll
        for (int j = 0; j < 3; j++) {
            int id  = tid + j * 128;
            int arr = id >> 7;          // 0:whi 1:wlo 2:fx
            int l   = id & 127;
            int row = l >> 3;
            int gr  = l & 7;
            uint32_t saddr = st + arr * 2048 + row * 128 + ((gr ^ (row & 7)) << 4);
            int n = nbase + t0 + row;
            const __nv_bfloat16* g;
            if (arr < 2) {
                g = (arr == 0 ? whi : wlo) + ((size_t)bh * NN + n) * GG + gr * 8;
            } else {
                g = fx + ((size_t)b * NN + n) * INNER + h * DH + gr * 8;
            }
            cp16(saddr, g, true);
        }
    };

    load(sbase, 0);
    asm volatile("cp.async.commit_group;\n" ::: "memory");

    for (int it = 0; it < 64; ++it) {
        const int cur = it & 1;
        if (it + 1 < 64) {
            load(sbase + (uint32_t)(1 - cur) * 6144, (it + 1) * 16);
            asm volatile("cp.async.commit_group;\n" ::: "memory");
            asm volatile("cp.async.wait_group 1;\n" ::: "memory");
        } else {
            asm volatile("cp.async.wait_group 0;\n" ::: "memory");
        }
        __syncthreads();

        const uint32_t st = sbase + (uint32_t)cur * 6144;

        uint32_t awh[4], awl[4];
        {
            int gr = wid * 2 + lgr;
            uint32_t addr = st + lrow * 128 + ((gr ^ (lrow & 7)) << 4);
            ldsm4t(awh, addr);
            ldsm4t(awl, addr + 2048);
        }
        mma_bf16(accn, awh[0], awh[1], awh[2], awh[3], ONES, ONES);
        mma_bf16(accn, awl[0], awl[1], awl[2], awl[3], ONES, ONES);

        #pragma unroll
        for (int j = 0; j < 4; j++) {
            int gr = j * 2 + lgr;
            uint32_t addr = st + 4096 + lrow * 128 + ((gr ^ (lrow & 7)) << 4);
            uint32_t bf[4];
            ldsm4t(bf, addr);
            mma_bf16(acc[2 * j],     awh[0], awh[1], awh[2], awh[3], bf[0], bf[2]);
            mma_bf16(acc[2 * j + 1], awh[0], awh[1], awh[2], awh[3], bf[1], bf[3]);
            mma_bf16(acc[2 * j],     awl[0], awl[1], awl[2], awl[3], bf[0], bf[2]);
            mma_bf16(acc[2 * j + 1], awl[0], awl[1], awl[2], awl[3], bf[1], bf[3]);
        }
        __syncthreads();
    }

    const size_t base = ((size_t)split * (BB * HEADS) + bh) * (GG * DH);
    const int g0 = wid * 16 + grp;
    #pragma unroll
    for (int nf = 0; nf < 8; nf++) {
        int d = (nf >> 1) * 16 + (nf & 1) * 8 + tid4 * 2;
        tokp[base + (size_t)g0 * DH + d]           = acc[nf][0];
        tokp[base + (size_t)g0 * DH + d + 1]       = acc[nf][1];
        tokp[base + (size_t)(g0 + 8) * DH + d]     = acc[nf][2];
        tokp[base + (size_t)(g0 + 8) * DH + d + 1] = acc[nf][3];
    }
    if (tid4 == 0) {
        size_t nb = ((size_t)split * (BB * HEADS) + bh) * GG;
        normp[nb + g0]     = accn[0];
        normp[nb + g0 + 8] = accn[2];
    }
}

// ---------------- K3b: deterministic split reduction ----------------
__global__ void split_reduce_kernel(const float* __restrict__ tokp,
                                    const float* __restrict__ normp,
                                    float* __restrict__ tok,
                                    float* __restrict__ norm) {
    const int blk = blockIdx.x;
    const int tid = threadIdx.x;
    if (blk < 256) {
        int idx = blk * 256 + tid;
        float s = 0.f;
        #pragma unroll 8
        for (int sp = 0; sp < SPLITS; sp++)
            s += tokp[(size_t)sp * 65536 + idx];
        tok[idx] = s;
    } else {
        int idx = (blk - 256) * 256 + tid;
        float s = 0.f;
        #pragma unroll 8
        for (int sp = 0; sp < SPLITS; sp++)
            s += normp[(size_t)sp * 1024 + idx];
        norm[idx] = s;
    }
}

// ---------------- K4: tiny attention per (b,h), emits Mt bf16 hi/lo ----------------
__global__ void attn_kernel(const float* __restrict__ tok,
                            const float* __restrict__ norm,
                            const float* __restrict__ Wq,
                            const float* __restrict__ Wk,
                            const float* __restrict__ Wv,
                            const float* __restrict__ Wout,
                            __nv_bfloat16* __restrict__ Mthi,
                            __nv_bfloat16* __restrict__ Mtlo) {
    const int bh = blockIdx.x;
    const int b = bh >> 3, h = bh & 7;
    const int tx = threadIdx.x, ty = threadIdx.y;
    const int tid = ty * 16 + tx;

    __shared__ float A[64][65];
    __shared__ float Bm[64][65];
    __shared__ float Cm[64][65];

    #pragma unroll
    for (int e = 0; e < 16; e++) {
        int idx = tid + e * 256;
        int g = idx >> 6, d = idx & 63;
        A[g][d] = tok[(size_t)bh * 4096 + idx] / (norm[bh * 64 + g] + 1e-5f);
    }
    __syncthreads();

    {
        float aq[4][4] = {}, ak[4][4] = {};
        #pragma unroll
        for (int kk = 0; kk < 64; kk++) {
            float a[4];
            #pragma unroll
            for (int i = 0; i < 4; i++) a[i] = A[ty + 16 * i][kk];
            #pragma unroll
            for (int j = 0; j < 4; j++) {
                float wq = __ldg(&Wq[(tx + 16 * j) * 64 + kk]);
                float wk = __ldg(&Wk[(tx + 16 * j) * 64 + kk]);
                #pragma unroll
                for (int i = 0; i < 4; i++) {
                    aq[i][j] += a[i] * wq;
                    ak[i][j] += a[i] * wk;
                }
            }
        }
        #pragma unroll
        for (int i = 0; i < 4; i++)
            #pragma unroll
            for (int j = 0; j < 4; j++) {
                Bm[ty + 16 * i][tx + 16 * j] = aq[i][j];
                Cm[ty + 16 * i][tx + 16 * j] = ak[i][j];
            }
    }
    __syncthreads();

    {
        float L[4][4] = {};
        #pragma unroll
        for (int kk = 0; kk < 64; kk++) {
            float a[4], bv[4];
            #pragma unroll
            for (int i = 0; i < 4; i++) a[i] = Bm[ty + 16 * i][kk];
            #pragma unroll
            for (int j = 0; j < 4; j++) bv[j] = Cm[tx + 16 * j][kk];
            #pragma unroll
            for (int i = 0; i < 4; i++)
                #pragma unroll
                for (int j = 0; j < 4; j++)
                    L[i][j] += a[i] * bv[j];
        }
        #pragma unroll
        for (int i = 0; i < 4; i++) {
            #pragma unroll
            for (int j = 0; j < 4; j++) L[i][j] *= 0.125f;
            float mx = L[i][0];
            #pragma unroll
            for (int j = 1; j < 4; j++) mx = fmaxf(mx, L[i][j]);
            #pragma unroll
            for (int o = 1; o < 16; o <<= 1)
                mx = fmaxf(mx, __shfl_xor_sync(0xffffffffu, mx, o, 16));
            float s = 0.f;
            #pragma unroll
            for (int j = 0; j < 4; j++) { L[i][j] = __expf(L[i][j] - mx); s += L[i][j]; }
            #pragma unroll
            for (int o = 1; o < 16; o <<= 1)
                s += __shfl_xor_sync(0xffffffffu, s, o, 16);
            float inv = 1.0f / s;
            #pragma unroll
            for (int j = 0; j < 4; j++)
                A[ty + 16 * i][tx + 16 * j] = L[i][j] * inv;
        }
    }
    __syncthreads();

    #pragma unroll
    for (int e = 0; e < 16; e++) {
        int idx = tid + e * 256;
        int g = idx >> 6;
        Bm[g][idx & 63] = tok[(size_t)bh * 4096 + idx] / (norm[bh * 64 + g] + 1e-5f);
    }
    __syncthreads();

    {
        float av[4][4] = {};
        #pragma unroll
        for (int kk = 0; kk < 64; kk++) {
            float a[4];
            #pragma unroll
            for (int i = 0; i < 4; i++) a[i] = Bm[ty + 16 * i][kk];
            #pragma unroll
            for (int j = 0; j < 4; j++) {
                float wv = __ldg(&Wv[(tx + 16 * j) * 64 + kk]);
                #pragma unroll
                for (int i = 0; i < 4; i++) av[i][j] += a[i] * wv;
            }
        }
        __syncthreads();
        #pragma unroll
        for (int i = 0; i < 4; i++)
            #pragma unroll
            for (int j = 0; j < 4; j++)
                Cm[ty + 16 * i][tx + 16 * j] = av[i][j];
    }
    __syncthreads();

    {
        float ao[4][4] = {};
        #pragma unroll
        for (int kk = 0; kk < 64; kk++) {
            float a[4], bv[4];
            #pragma unroll
            for (int i = 0; i < 4; i++) a[i] = A[ty + 16 * i][kk];
            #pragma unroll
            for (int j = 0; j < 4; j++) bv[j] = Cm[kk][tx + 16 * j];
            #pragma unroll
            for (int i = 0; i < 4; i++)
                #pragma unroll
                for (int j = 0; j < 4; j++)
                    ao[i][j] += a[i] * bv[j];
        }
        __syncthreads();
        #pragma unroll
        for (int i = 0; i < 4; i++)
            #pragma unroll
            for (int j = 0; j < 4; j++)
                Bm[ty + 16 * i][tx + 16 * j] = ao[i][j];
    }
    __syncthreads();

    {
        float am[4][8] = {};
        #pragma unroll
        for (int kk = 0; kk < 64; kk++) {
            float a[4];
            #pragma unroll
            for (int i = 0; i < 4; i++) a[i] = Bm[ty + 16 * i][kk];
            #pragma unroll
            for (int j = 0; j < 8; j++) {
                float wv = __ldg(&Wout[(size_t)(tx + 16 * j) * INNER + h * DH + kk]);
                #pragma unroll
                for (int i = 0; i < 4; i++) am[i][j] += a[i] * wv;
            }
        }
        #pragma unroll
        for (int i = 0; i < 4; i++) {
            int g = ty + 16 * i;
            #pragma unroll
            for (int j = 0; j < 8; j++) {
                int o = tx + 16 * j;
                float v = am[i][j];
                __nv_bfloat16 hv = __float2bfloat16(v);
                float r = v - __bfloat162float(hv);
                size_t idx = ((size_t)b * CC + o) * INNER + h * DH + g;
                Mthi[idx] = hv;
                Mtlo[idx] = __float2bfloat16(r);
            }
        }
    }
}

// ---------------- K5: fused scatter + projection, kc=32, 4 warps, 2 CTAs/SM ----------------
#define FSTAGE 32768
#define FNCHUNK 16

__device__ __forceinline__ void fin_load(
    uint32_t st,
    const __nv_bfloat16* __restrict__ Whi, const __nv_bfloat16* __restrict__ Wlo,
    const __nv_bfloat16* __restrict__ Mthi, const __nv_bfloat16* __restrict__ Mtlo,
    int it, int b, int n0, int tid)
{
    const int h  = it >> 1;
    const int g0 = (it & 1) * 32;

    #pragma unroll
    for (int j = 0; j < 8; j++) {
        int id  = tid + j * 128;
        int arr = id >> 9;              // 0:whi 1:wlo
        int l   = id & 511;
        int row = l >> 2;
        int gr  = l & 3;
        uint32_t saddr = st + arr * 8192 + sw32(row, gr);
        const __nv_bfloat16* g = (arr == 0 ? Whi : Wlo) +
            (((size_t)(b * HEADS + h) * NN) + n0 + row) * GG + g0 + gr * 8;
        cp16(saddr, g, true);
    }
    #pragma unroll
    for (int j = 0; j < 8; j++) {
        int id  = tid + j * 128;
        int arr = id >> 9;              // 0:Mthi 1:Mtlo
        int l   = id & 511;
        int row = l >> 2;
        int gr  = l & 3;
        uint32_t saddr = st + 16384 + arr * 8192 + sw32(row, gr);
        const __nv_bfloat16* g = (arr == 0 ? Mthi : Mtlo) +
            ((size_t)b * CC + row) * INNER + h * DH + g0 + gr * 8;
        cp16(saddr, g, true);
    }
}

__global__ __launch_bounds__(128, 2)
void final_mma_kernel(const __nv_bfloat16* __restrict__ Whi,
                      const __nv_bfloat16* __restrict__ Wlo,
                      const __nv_bfloat16* __restrict__ Mthi,
                      const __nv_bfloat16* __restrict__ Mtlo,
                      const float* __restrict__ bout,
                      float* __restrict__ out)
{
    extern __shared__ char smem[];           // 3 stages x 32KB

    const int pt = blockIdx.x;
    const int b  = pt >> 9;
    const int n0 = (pt & 511) * 128;

    const int tid  = threadIdx.x;            // 0..127
    const int wid  = tid >> 5;
    const int lane = tid & 31;
    const int grp  = lane >> 2;
    const int tid4 = lane & 3;
    const int wm   = wid & 1;                // 2 row-groups of 64
    const int wn   = wid >> 1;               // 2 col-groups of 64

    const int t8   = lane >> 3;
    const int r8   = lane & 7;
    const int a_roff = ((t8 & 1) << 3) + r8;
    const int a_gsel = t8 >> 1;
    const int b_roff = ((t8 >> 1) << 3) + r8;
    const int b_gsel = t8 & 1;

    float acc[4][8][4];
    #pragma unroll
    for (int i = 0; i < 4; i++)
        #pragma unroll
        for (int j = 0; j < 8; j++)
            #pragma unroll
            for (int r = 0; r < 4; r++) acc[i][j][r] = 0.f;

    uint32_t sbase = (uint32_t)__cvta_generic_to_shared(smem);

    fin_load(sbase, Whi, Wlo, Mthi, Mtlo, 0, b, n0, tid);
    asm volatile("cp.async.commit_group;\n" ::: "memory");
    fin_load(sbase + FSTAGE, Whi, Wlo, Mthi, Mtlo, 1, b, n0, tid);
    asm volatile("cp.async.commit_group;\n" ::: "memory");

    for (int it = 0; it < FNCHUNK; ++it) {
        const int cur = it % 3;
        if (it + 2 < FNCHUNK)
            fin_load(sbase + (uint32_t)((it + 2) % 3) * FSTAGE,
                     Whi, Wlo, Mthi, Mtlo, it + 2, b, n0, tid);
        asm volatile("cp.async.commit_group;\n" ::: "memory");
        asm volatile("cp.async.wait_group 2;\n" ::: "memory");
        __syncthreads();

        const uint32_t stA = sbase + (uint32_t)cur * FSTAGE;
        const uint32_t stB = stA + 16384;

        #pragma unroll
        for (int s = 0; s < 2; s++) {
            uint32_t ah[4][4], al[4][4];
            #pragma unroll
            for (int mi = 0; mi < 4; mi++) {
                int row = wm * 64 + mi * 16 + a_roff;
                int g = 2 * s + a_gsel;
                uint32_t addr = stA + sw32(row, g);
                ldsm4(ah[mi], addr);
                ldsm4(al[mi], addr + 8192);
            }
            #pragma unroll
            for (int np = 0; np < 4; np++) {
                int row = wn * 64 + np * 16 + b_roff;
                int g = 2 * s + b_gsel;
                uint32_t addr = stB + sw32(row, g);
                uint32_t bh[4], bl[4];
                ldsm4(bh, addr);
                ldsm4(bl, addr + 8192);
                #pragma unroll
                for (int mi = 0; mi < 4; mi++) {
                    mma_bf16(acc[mi][2 * np],     ah[mi][0], ah[mi][1], ah[mi][2], ah[mi][3], bh[0], bh[1]);
                    mma_bf16(acc[mi][2 * np + 1], ah[mi][0], ah[mi][1], ah[mi][2], ah[mi][3], bh[2], bh[3]);
                }
                #pragma unroll
                for (int mi = 0; mi < 4; mi++) {
                    mma_bf16(acc[mi][2 * np],     ah[mi][0], ah[mi][1], ah[mi][2], ah[mi][3], bl[0], bl[1]);
                    mma_bf16(acc[mi][2 * np + 1], ah[mi][0], ah[mi][1], ah[mi][2], ah[mi][3], bl[2], bl[3]);
                }
                #pragma unroll
                for (int mi = 0; mi < 4; mi++) {
                    mma_bf16(acc[mi][2 * np],     al[mi][0], al[mi][1], al[mi][2], al[mi][3], bh[0], bh[1]);
                    mma_bf16(acc[mi][2 * np + 1], al[mi][0], al[mi][1], al[mi][2], al[mi][3], bh[2], bh[3]);
                }
            }
        }
        __syncthreads();
    }

    #pragma unroll
    for (int mi = 0; mi < 4; mi++) {
        int row = wm * 64 + mi * 16 + grp;
        int n  = n0 + row;
        #pragma unroll
        for (int ni = 0; ni < 8; ni++) {
            int oc = wn * 64 + ni * 8 + tid4 * 2;
            float b0v = bout[oc], b1v = bout[oc + 1];
            size_t base0 = ((size_t)b * NN + n) * CC + oc;
            out[base0]     = acc[mi][ni][0] + b0v;
            out[base0 + 1] = acc[mi][ni][1] + b1v;
            size_t base1 = ((size_t)b * NN + n + 8) * CC + oc;
            out[base1]     = acc[mi][ni][2] + b0v;
            out[base1 + 1] = acc[mi][ni][3] + b1v;
        }
    }
}

// ---------------- launch ----------------
extern "C" void kernel_launch(void* const* d_in, const int* in_sizes, int n_in,
                              void* d_out, int out_size) {
    const float* x     = (const float*)d_in[0];
    const float* Wfx   = (const float*)d_in[1];
    const float* bfx   = (const float*)d_in[2];
    const float* Wx    = (const float*)d_in[3];
    const float* bx    = (const float*)d_in[4];
    const float* Wsl   = (const float*)d_in[5];
    const float* bsl   = (const float*)d_in[6];
    const float* temp  = (const float*)d_in[7];
    const float* Wq    = (const float*)d_in[8];
    const float* Wk    = (const float*)d_in[9];
    const float* Wv    = (const float*)d_in[10];
    const float* Wout  = (const float*)d_in[11];
    const float* bout  = (const float*)d_in[12];
    float* out = (float*)d_out;

    float *p_tokp, *p_normp, *p_tok, *p_norm, *p_lb;
    __nv_bfloat16 *p_xhi, *p_xlo, *p_whi, *p_wlo;
    __nv_bfloat16 *p_fxhi;
    __nv_bfloat16 *p_swhi, *p_swlo, *p_Mthi, *p_Mtlo;
    cudaGetSymbolAddress((void**)&p_tokp, g_tokp);
    cudaGetSymbolAddress((void**)&p_normp, g_normp);
    cudaGetSymbolAddress((void**)&p_tok, g_tok);
    cudaGetSymbolAddress((void**)&p_norm, g_norm);
    cudaGetSymbolAddress((void**)&p_lb, g_lbias);
    cudaGetSymbolAddress((void**)&p_xhi, g_xhi);
    cudaGetSymbolAddress((void**)&p_xlo, g_xlo);
    cudaGetSymbolAddress((void**)&p_whi, g_whi);
    cudaGetSymbolAddress((void**)&p_wlo, g_wlo);
    cudaGetSymbolAddress((void**)&p_fxhi, g_fxhi);
    cudaGetSymbolAddress((void**)&p_swhi, g_swhi);
    cudaGetSymbolAddress((void**)&p_swlo, g_swlo);
    cudaGetSymbolAddress((void**)&p_Mthi, g_Mthi);
    cudaGetSymbolAddress((void**)&p_Mtlo, g_Mtlo);

    static bool attr_set = false;
    if (!attr_set) {
        cudaFuncSetAttribute(conv_mma_kernel,
                             cudaFuncAttributeMaxDynamicSharedMemorySize, CSMEM);
        cudaFuncSetAttribute(final_mma_kernel,
                             cudaFuncAttributeMaxDynamicSharedMemorySize, 3 * FSTAGE);
        attr_set = true;
    }

    dim3 blk(16, 16);

    // 0. staging (3 launches; conv is launch #4 for ncu visibility)
    split_x_kernel<<<(BB * NN * CC) / 256, 256>>>(x, p_xhi, p_xlo);
    split_w_kernel<<<(512 * KTOT) / 256, 256>>>(Wfx, p_whi, p_wlo);
    combine_w_kernel<<<dim3(512, 10), 128>>>(Wx, Wsl, bx, bsl, temp, p_whi, p_wlo, p_lb);

    // 1. fused conv (launch #4): 128x128 tiles, 4 warps, 3 CTAs/SM, 2-stage
    conv_mma_kernel<<<dim3(8, 512, BB), 128, CSMEM>>>(
        p_xhi, p_xlo, p_whi, p_wlo, bfx, p_lb, p_fxhi, p_swhi, p_swlo);

    // 2. slice token reduction on tensor cores + split reduce
    token_mma_kernel<<<dim3(SPLITS, BB * HEADS), 128>>>(
        p_swhi, p_swlo, p_fxhi, p_tokp, p_normp);
    split_reduce_kernel<<<260, 256>>>(p_tokp, p_normp, p_tok, p_norm);

    // 3. tiny attention + fused Wout fold -> Mt (bf16 hi/lo)
    attn_kernel<<<BB * HEADS, blk>>>(p_tok, p_norm, Wq, Wk, Wv, Wout, p_Mthi, p_Mtlo);

    // 4. fused scatter + projection: kc=32, 4 warps, 2 CTAs/SM, 3-stage
    final_mma_kernel<<<1024, 128, 3 * FSTAGE>>>(p_swhi, p_swlo, p_Mthi, p_Mtlo, bout, out);
}

// round 16
// speedup vs baseline: 1.1246x; 1.1246x over previous
#include <cuda_runtime.h>
#include <cuda_bf16.h>
#include <math.h>
#include <stdint.h>

// Problem constants
#define BB 2
#define HH 256
#define WW 256
#define NN 65536          // H*W
#define CC 128
#define HEADS 8
#define DH 64             // dim_head
#define GG 64             // SLICE
#define INNER 512         // HEADS*DH
#define SPLITS 64         // split-K for token reduction
#define CHUNK 1024        // tokens per split (NN/SPLITS)
#define KTOT 1152         // 9 taps * 128 channels

// ---------------- device scratch (static, no allocs) ----------------
__device__ float g_tokp[(size_t)SPLITS * BB * HEADS * GG * DH];
__device__ float g_normp[(size_t)SPLITS * BB * HEADS * GG];
__device__ float g_tok [(size_t)BB * HEADS * GG * DH];
__device__ float g_norm[(size_t)BB * HEADS * GG];
__device__ float g_lbias[INNER];                     // (bx·Wslice + bslice)/temp

// fx_mid as single bf16  [b][n][inner]
__device__ __align__(16) __nv_bfloat16 g_fxhi[(size_t)BB * NN * INNER];
// slice weights as bf16 hi/lo pair  [bh][n][g]
__device__ __align__(16) __nv_bfloat16 g_swhi[(size_t)BB * HEADS * NN * GG];
__device__ __align__(16) __nv_bfloat16 g_swlo[(size_t)BB * HEADS * NN * GG];
// Mt = (out_slice · Wout^T) transposed: [b][o][h*64+g], bf16 hi/lo
__device__ __align__(16) __nv_bfloat16 g_Mthi[(size_t)BB * CC * INNER];
__device__ __align__(16) __nv_bfloat16 g_Mtlo[(size_t)BB * CC * INNER];

// bf16 3-split staging for conv
__device__ __align__(16) __nv_bfloat16 g_xhi[(size_t)BB * NN * CC];
__device__ __align__(16) __nv_bfloat16 g_xlo[(size_t)BB * NN * CC];
// rows 0..511: Wfx cols; rows 512..1023: combined logit weights (Wx·Wslice/temp)
__device__ __align__(16) __nv_bfloat16 g_whi[(size_t)1024 * KTOT];
__device__ __align__(16) __nv_bfloat16 g_wlo[(size_t)1024 * KTOT];

// ---------------- prep kernels ----------------
// vectorized 4x: float4 in, packed 4xbf16 (uint2) out
__global__ void split_x_kernel(const float4* __restrict__ x,
                               uint2* __restrict__ xhi,
                               uint2* __restrict__ xlo) {
    size_t i = (size_t)blockIdx.x * 256 + threadIdx.x;
    float4 f = x[i];
    union { __nv_bfloat16 hb[4]; uint2 u; } Uh, Ul;
    Uh.hb[0] = __float2bfloat16(f.x);
    Uh.hb[1] = __float2bfloat16(f.y);
    Uh.hb[2] = __float2bfloat16(f.z);
    Uh.hb[3] = __float2bfloat16(f.w);
    Ul.hb[0] = __float2bfloat16(f.x - __bfloat162float(Uh.hb[0]));
    Ul.hb[1] = __float2bfloat16(f.y - __bfloat162float(Uh.hb[1]));
    Ul.hb[2] = __float2bfloat16(f.z - __bfloat162float(Uh.hb[2]));
    Ul.hb[3] = __float2bfloat16(f.w - __bfloat162float(Uh.hb[3]));
    xhi[i] = Uh.u;
    xlo[i] = Ul.u;
}

__global__ void split_w_kernel(const float* __restrict__ Wfx,
                               __nv_bfloat16* __restrict__ whi,
                               __nv_bfloat16* __restrict__ wlo) {
    int i = blockIdx.x * 256 + threadIdx.x;   // 512*1152 total
    int oc = i / KTOT;
    int k  = i - oc * KTOT;
    float f = Wfx[(size_t)k * 512 + oc];
    __nv_bfloat16 h = __float2bfloat16(f);
    float r = f - __bfloat162float(h);
    whi[i] = h;
    wlo[i] = __float2bfloat16(r);
}

__global__ void combine_w_kernel(const float* __restrict__ Wx,
                                 const float* __restrict__ Wsl,
                                 const float* __restrict__ bx,
                                 const float* __restrict__ bsl,
                                 const float* __restrict__ temp,
                                 __nv_bfloat16* __restrict__ whi,
                                 __nv_bfloat16* __restrict__ wlo,
                                 float* __restrict__ lb) {
    __shared__ float ws[64];
    const int col = blockIdx.x;          // 0..511
    const int h = col >> 6, g = col & 63;
    const int tid = threadIdx.x;         // 128
    if (tid < 64) ws[tid] = Wsl[g * 64 + tid];
    __syncthreads();
    float t = fminf(fmaxf(temp[h], 0.1f), 5.0f);
    float invt = 1.0f / t;

    if (blockIdx.y == 9) {
        if (tid < 32) {
            float s = bx[h * 64 + tid] * ws[tid]
                    + bx[h * 64 + 32 + tid] * ws[32 + tid];
            #pragma unroll
            for (int o = 16; o > 0; o >>= 1)
                s += __shfl_xor_sync(0xffffffffu, s, o);
            if (tid == 0) lb[col] = (s + bsl[g]) * invt;
        }
        return;
    }

    int k = blockIdx.y * 128 + tid;      // 9 y-blocks -> 0..1151
    const float* wr = Wx + (size_t)k * 512 + h * 64;
    float s = 0.f;
    #pragma unroll 8
    for (int d = 0; d < 64; d++) s += wr[d] * ws[d];
    s *= invt;
    __nv_bfloat16 hv = __float2bfloat16(s);
    size_t o = (size_t)(512 + col) * KTOT + k;
    whi[o] = hv;
    wlo[o] = __float2bfloat16(s - __bfloat162float(hv));
}

// ---------------- shared MMA plumbing ----------------
__device__ __forceinline__ void cp16(uint32_t saddr, const void* g, bool valid) {
    int sz = valid ? 16 : 0;
    asm volatile("cp.async.cg.shared.global [%0], [%1], 16, %2;\n"
                 :: "r"(saddr), "l"(g), "r"(sz));
}

__device__ __forceinline__ void mma_bf16(float c[4], uint32_t a0, uint32_t a1,
                                         uint32_t a2, uint32_t a3,
                                         uint32_t b0, uint32_t b1) {
    asm volatile(
        "mma.sync.aligned.m16n8k16.row.col.f32.bf16.bf16.f32 "
        "{%0,%1,%2,%3}, {%4,%5,%6,%7}, {%8,%9}, {%0,%1,%2,%3};"
        : "+f"(c[0]), "+f"(c[1]), "+f"(c[2]), "+f"(c[3])
        : "r"(a0), "r"(a1), "r"(a2), "r"(a3), "r"(b0), "r"(b1));
}

__device__ __forceinline__ void ldsm4(uint32_t r[4], uint32_t addr) {
    asm volatile("ldmatrix.sync.aligned.m8n8.x4.shared.b16 {%0,%1,%2,%3}, [%4];"
                 : "=r"(r[0]), "=r"(r[1]), "=r"(r[2]), "=r"(r[3]) : "r"(addr));
}

__device__ __forceinline__ void ldsm4t(uint32_t r[4], uint32_t addr) {
    asm volatile("ldmatrix.sync.aligned.m8n8.x4.trans.shared.b16 {%0,%1,%2,%3}, [%4];"
                 : "=r"(r[0]), "=r"(r[1]), "=r"(r[2]), "=r"(r[3]) : "r"(addr));
}

// packed kc=32 tile: 128 logical rows x 32 bf16, two logical rows per 128B phys row.
__device__ __forceinline__ uint32_t sw32(int row, int gr) {
    return (uint32_t)(row >> 1) * 128 +
           (uint32_t)(((gr | ((row & 1) << 2)) ^ ((row >> 1) & 7)) << 4);
}

// ---------------- conv: implicit GEMM 128x128, kc=32, 4 warps, 2 CTAs/SM ----------------
#define CSTAGE 32768
#define NCHUNK 36

__device__ __forceinline__ void conv_load(
    uint32_t st,
    const __nv_bfloat16* __restrict__ Xhi, const __nv_bfloat16* __restrict__ Xlo,
    const __nv_bfloat16* __restrict__ Whi, const __nv_bfloat16* __restrict__ Wlo,
    int it, int b, int hrow, int w0, int ocb, int tid)
{
    const int kg  = it * 32;
    const int tap = kg >> 7;
    const int dy = tap / 3 - 1, dx = tap % 3 - 1;
    const int c0 = kg & 127;            // 0/32/64/96
    const int hp = hrow + dy;
    const bool hok = (hp >= 0) && (hp < HH);
    const int hpc = hok ? hp : 0;

    #pragma unroll
    for (int j = 0; j < 8; j++) {
        int id  = tid + j * 128;
        int arr = id >> 9;              // 0:Ahi 1:Alo
        int l   = id & 511;
        int row = l >> 2;
        int gr  = l & 3;
        uint32_t saddr = st + arr * 8192 + sw32(row, gr);
        int wp = w0 + row + dx;
        bool valid = hok && (wp >= 0) && (wp < WW);
        int wpc = valid ? wp : 0;
        const __nv_bfloat16* g = (arr == 0 ? Xhi : Xlo) +
            (((size_t)b * NN + (size_t)hpc * WW + wpc) * CC + c0 + gr * 8);
        cp16(saddr, g, valid);
    }
    #pragma unroll
    for (int j = 0; j < 8; j++) {
        int id  = tid + j * 128;
        int arr = id >> 9;              // 0:Bhi 1:Blo
        int l   = id & 511;
        int row = l >> 2;
        int gr  = l & 3;
        uint32_t saddr = st + 16384 + arr * 8192 + sw32(row, gr);
        const __nv_bfloat16* g = (arr == 0 ? Whi : Wlo) +
            ((size_t)(ocb * 128 + row) * KTOT + kg + gr * 8);
        cp16(saddr, g, true);
    }
}

__global__ __launch_bounds__(128, 2)
void conv_mma_kernel(const __nv_bfloat16* __restrict__ Xhi,
                     const __nv_bfloat16* __restrict__ Xlo,
                     const __nv_bfloat16* __restrict__ Whi,
                     const __nv_bfloat16* __restrict__ Wlo,
                     const float* __restrict__ bfx,
                     const float* __restrict__ lbias,
                     __nv_bfloat16* __restrict__ fxhi,
                     __nv_bfloat16* __restrict__ swhi,
                     __nv_bfloat16* __restrict__ swlo)
{
    extern __shared__ char smem[];           // 3 stages x 32KB

    const int ocb = blockIdx.x;              // 0..7
    const int pt  = blockIdx.y;              // 0..511
    const int b   = blockIdx.z;
    const int n0  = pt * 128;
    const int hrow = n0 >> 8;
    const int w0   = n0 & 255;

    const int tid  = threadIdx.x;            // 0..127
    const int wid  = tid >> 5;               // 0..3
    const int lane = tid & 31;
    const int grp  = lane >> 2;
    const int tid4 = lane & 3;
    const int wm   = wid & 1;                // 2 row-groups of 64
    const int wn   = wid >> 1;               // 2 col-groups of 64

    const int t8   = lane >> 3;
    const int r8   = lane & 7;
    const int a_roff = ((t8 & 1) << 3) + r8;
    const int a_gsel = t8 >> 1;
    const int b_roff = ((t8 >> 1) << 3) + r8;
    const int b_gsel = t8 & 1;

    float acc[4][8][4];
    #pragma unroll
    for (int i = 0; i < 4; i++)
        #pragma unroll
        for (int j = 0; j < 8; j++)
            #pragma unroll
            for (int r = 0; r < 4; r++) acc[i][j][r] = 0.f;

    uint32_t sbase = (uint32_t)__cvta_generic_to_shared(smem);

    conv_load(sbase, Xhi, Xlo, Whi, Wlo, 0, b, hrow, w0, ocb, tid);
    asm volatile("cp.async.commit_group;\n" ::: "memory");
    conv_load(sbase + CSTAGE, Xhi, Xlo, Whi, Wlo, 1, b, hrow, w0, ocb, tid);
    asm volatile("cp.async.commit_group;\n" ::: "memory");

    for (int it = 0; it < NCHUNK; ++it) {
        const int cur = it % 3;
        if (it + 2 < NCHUNK)
            conv_load(sbase + (uint32_t)((it + 2) % 3) * CSTAGE,
                      Xhi, Xlo, Whi, Wlo, it + 2, b, hrow, w0, ocb, tid);
        asm volatile("cp.async.commit_group;\n" ::: "memory");
        asm volatile("cp.async.wait_group 2;\n" ::: "memory");
        __syncthreads();

        const uint32_t stA = sbase + (uint32_t)cur * CSTAGE;
        const uint32_t stB = stA + 16384;

        #pragma unroll
        for (int s = 0; s < 2; s++) {
            uint32_t ah[4][4], al[4][4];
            #pragma unroll
            for (int mi = 0; mi < 4; mi++) {
                int row = wm * 64 + mi * 16 + a_roff;
                int g = 2 * s + a_gsel;
                uint32_t addr = stA + sw32(row, g);
                ldsm4(ah[mi], addr);
                ldsm4(al[mi], addr + 8192);
            }
            #pragma unroll
            for (int np = 0; np < 4; np++) {
                int row = wn * 64 + np * 16 + b_roff;
                int g = 2 * s + b_gsel;
                uint32_t addr = stB + sw32(row, g);
                uint32_t bh[4], bl[4];
                ldsm4(bh, addr);
                ldsm4(bl, addr + 8192);
                #pragma unroll
                for (int mi = 0; mi < 4; mi++) {
                    mma_bf16(acc[mi][2 * np],     ah[mi][0], ah[mi][1], ah[mi][2], ah[mi][3], bh[0], bh[1]);
                    mma_bf16(acc[mi][2 * np + 1], ah[mi][0], ah[mi][1], ah[mi][2], ah[mi][3], bh[2], bh[3]);
                }
                #pragma unroll
                for (int mi = 0; mi < 4; mi++) {
                    mma_bf16(acc[mi][2 * np],     ah[mi][0], ah[mi][1], ah[mi][2], ah[mi][3], bl[0], bl[1]);
                    mma_bf16(acc[mi][2 * np + 1], ah[mi][0], ah[mi][1], ah[mi][2], ah[mi][3], bl[2], bl[3]);
                }
                #pragma unroll
                for (int mi = 0; mi < 4; mi++) {
                    mma_bf16(acc[mi][2 * np],     al[mi][0], al[mi][1], al[mi][2], al[mi][3], bh[0], bh[1]);
                    mma_bf16(acc[mi][2 * np + 1], al[mi][0], al[mi][1], al[mi][2], al[mi][3], bh[2], bh[3]);
                }
            }
        }
        __syncthreads();
    }

    if (ocb < 4) {
        const int ocbase = ocb * 128;
        #pragma unroll
        for (int mi = 0; mi < 4; mi++) {
            int row = wm * 64 + mi * 16 + grp;
            int n  = n0 + row;
            #pragma unroll
            for (int ni = 0; ni < 8; ni++) {
                int col = wn * 64 + ni * 8 + tid4 * 2;
                int oc  = ocbase + col;
                float b0v = bfx[oc], b1v = bfx[oc + 1];
                __nv_bfloat162 p0;
                p0.x = __float2bfloat16(acc[mi][ni][0] + b0v);
                p0.y = __float2bfloat16(acc[mi][ni][1] + b1v);
                __nv_bfloat162 p1;
                p1.x = __float2bfloat16(acc[mi][ni][2] + b0v);
                p1.y = __float2bfloat16(acc[mi][ni][3] + b1v);
                *(__nv_bfloat162*)(fxhi + ((size_t)b * NN + n) * INNER + oc) = p0;
                *(__nv_bfloat162*)(fxhi + ((size_t)b * NN + n + 8) * INNER + oc) = p1;
            }
        }
    } else {
        float* sred = (float*)smem;          // [128][132]
        #pragma unroll
        for (int mi = 0; mi < 4; mi++) {
            int row = wm * 64 + mi * 16 + grp;
            #pragma unroll
            for (int ni = 0; ni < 8; ni++) {
                int col = wn * 64 + ni * 8 + tid4 * 2;
                sred[row * 132 + col]           = acc[mi][ni][0];
                sred[row * 132 + col + 1]       = acc[mi][ni][1];
                sred[(row + 8) * 132 + col]     = acc[mi][ni][2];
                sred[(row + 8) * 132 + col + 1] = acc[mi][ni][3];
            }
        }
        __syncthreads();

        #pragma unroll
        for (int pass = 0; pass < 2; pass++) {
            int tsk = tid + pass * 128;      // 0..255
            int row  = tsk >> 1;
            int hloc = tsk & 1;
            int h = (ocb - 4) * 2 + hloc;
            int n = n0 + row;
            const float* lb = lbias + h * 64;
            float* sr = sred + row * 132 + hloc * 64;

            float mx = -1e30f;
            #pragma unroll 8
            for (int g = 0; g < 64; g++) mx = fmaxf(mx, sr[g] + lb[g]);
            float ssum = 0.f;
            #pragma unroll 8
            for (int g = 0; g < 64; g++) {
                float e = __expf(sr[g] + lb[g] - mx);
                ssum += e;
                sr[g] = e;
            }
            float inv = 1.0f / ssum;

            size_t base = ((size_t)(b * HEADS + h) * NN + n) * GG;
            #pragma unroll
            for (int c = 0; c < 8; c++) {
                union { __nv_bfloat16 hb[8]; uint4 u; } Uh, Ul;
                #pragma unroll
                for (int e = 0; e < 8; e++) {
                    float v = sr[c * 8 + e] * inv;
                    __nv_bfloat16 hv = __float2bfloat16(v);
                    Uh.hb[e] = hv;
                    Ul.hb[e] = __float2bfloat16(v - __bfloat162float(hv));
                }
                ((uint4*)(swhi + base))[c] = Uh.u;
                ((uint4*)(swlo + base))[c] = Ul.u;
            }
        }
    }
}

// ---------------- K3: token reduction on tensor cores (fx single bf16) ----------------
__global__ __launch_bounds__(128)
void token_mma_kernel(const __nv_bfloat16* __restrict__ whi,
                      const __nv_bfloat16* __restrict__ wlo,
                      const __nv_bfloat16* __restrict__ fx,
                      float* __restrict__ tokp,
                      float* __restrict__ normp)
{
    __shared__ __align__(16) char smem[2 * 6144];

    const int bh = blockIdx.y;
    const int b = bh >> 3, h = bh & 7;
    const int split = blockIdx.x;
    const int nbase = split * CHUNK;

    const int tid  = threadIdx.x;
    const int wid  = tid >> 5;          // 0..3: g-strip wid*16
    const int lane = tid & 31;
    const int grp  = lane >> 2;
    const int tid4 = lane & 3;
    const int t8   = lane >> 3;
    const int r8   = lane & 7;
    const int lrow = r8 + ((t8 >> 1) << 3);   // 0..15
    const int lgr  = t8 & 1;

    const uint32_t ONES = 0x3F803F80u;  // bf16(1.0) x2

    float acc[8][4];
    #pragma unroll
    for (int j = 0; j < 8; j++)
        #pragma unroll
        for (int r = 0; r < 4; r++) acc[j][r] = 0.f;
    float accn[4] = {};

    uint32_t sbase = (uint32_t)__cvta_generic_to_shared(smem);

    auto load = [&](uint32_t st, int t0) {
        #pragma unroll
        for (int j = 0; j < 3; j++) {
            int id  = tid + j * 128;
            int arr = id >> 7;          // 0:whi 1:wlo 2:fx
            int l   = id & 127;
            int row = l >> 3;
            int gr  = l & 7;
            uint32_t saddr = st + arr * 2048 + row * 128 + ((gr ^ (row & 7)) << 4);
            int n = nbase + t0 + row;
            const __nv_bfloat16* g;
            if (arr < 2) {
                g = (arr == 0 ? whi : wlo) + ((size_t)bh * NN + n) * GG + gr * 8;
            } else {
                g = fx + ((size_t)b * NN + n) * INNER + h * DH + gr * 8;
            }
            cp16(saddr, g, true);
        }
    };

    load(sbase, 0);
    asm volatile("cp.async.commit_group;\n" ::: "memory");

    for (int it = 0; it < 64; ++it) {
        const int cur = it & 1;
        if (it + 1 < 64) {
            load(sbase + (uint32_t)(1 - cur) * 6144, (it + 1) * 16);
            asm volatile("cp.async.commit_group;\n" ::: "memory");
            asm volatile("cp.async.wait_group 1;\n" ::: "memory");
        } else {
            asm volatile("cp.async.wait_group 0;\n" ::: "memory");
        }
        __syncthreads();

        const uint32_t st = sbase + (uint32_t)cur * 6144;

        uint32_t awh[4], awl[4];
        {
            int gr = wid * 2 + lgr;
            uint32_t addr = st + lrow * 128 + ((gr ^ (lrow & 7)) << 4);
            ldsm4t(awh, addr);
            ldsm4t(awl, addr + 2048);
        }
        mma_bf16(accn, awh[0], awh[1], awh[2], awh[3], ONES, ONES);
        mma_bf16(accn, awl[0], awl[1], awl[2], awl[3], ONES, ONES);

        #pragma unroll
        for (int j = 0; j < 4; j++) {
            int gr = j * 2 + lgr;
            uint32_t addr = st + 4096 + lrow * 128 + ((gr ^ (lrow & 7)) << 4);
            uint32_t bf[4];
            ldsm4t(bf, addr);
            mma_bf16(acc[2 * j],     awh[0], awh[1], awh[2], awh[3], bf[0], bf[2]);
            mma_bf16(acc[2 * j + 1], awh[0], awh[1], awh[2], awh[3], bf[1], bf[3]);
            mma_bf16(acc[2 * j],     awl[0], awl[1], awl[2], awl[3], bf[0], bf[2]);
            mma_bf16(acc[2 * j + 1], awl[0], awl[1], awl[2], awl[3], bf[1], bf[3]);
        }
        __syncthreads();
    }

    const size_t base = ((size_t)split * (BB * HEADS) + bh) * (GG * DH);
    const int g0 = wid * 16 + grp;
    #pragma unroll
    for (int nf = 0; nf < 8; nf++) {
        int d = (nf >> 1) * 16 + (nf & 1) * 8 + tid4 * 2;
        tokp[base + (size_t)g0 * DH + d]           = acc[nf][0];
        tokp[base + (size_t)g0 * DH + d + 1]       = acc[nf][1];
        tokp[base + (size_t)(g0 + 8) * DH + d]     = acc[nf][2];
        tokp[base + (size_t)(g0 + 8) * DH + d + 1] = acc[nf][3];
    }
    if (tid4 == 0) {
        size_t nb = ((size_t)split * (BB * HEADS) + bh) * GG;
        normp[nb + g0]     = accn[0];
        normp[nb + g0 + 8] = accn[2];
    }
}

// ---------------- K3b: deterministic split reduction ----------------
__global__ void split_reduce_kernel(const float* __restrict__ tokp,
                                    const float* __restrict__ normp,
                                    float* __restrict__ tok,
                                    float* __restrict__ norm) {
    const int blk = blockIdx.x;
    const int tid = threadIdx.x;
    if (blk < 256) {
        int idx = blk * 256 + tid;
        float s = 0.f;
        #pragma unroll 8
        for (int sp = 0; sp < SPLITS; sp++)
            s += tokp[(size_t)sp * 65536 + idx];
        tok[idx] = s;
    } else {
        int idx = (blk - 256) * 256 + tid;
        float s = 0.f;
        #pragma unroll 8
        for (int sp = 0; sp < SPLITS; sp++)
            s += normp[(size_t)sp * 1024 + idx];
        norm[idx] = s;
    }
}

// ---------------- K4: tiny attention per (b,h), emits Mt bf16 hi/lo ----------------
__global__ void attn_kernel(const float* __restrict__ tok,
                            const float* __restrict__ norm,
                            const float* __restrict__ Wq,
                            const float* __restrict__ Wk,
                            const float* __restrict__ Wv,
                            const float* __restrict__ Wout,
                            __nv_bfloat16* __restrict__ Mthi,
                            __nv_bfloat16* __restrict__ Mtlo) {
    const int bh = blockIdx.x;
    const int b = bh >> 3, h = bh & 7;
    const int tx = threadIdx.x, ty = threadIdx.y;
    const int tid = ty * 16 + tx;

    __shared__ float A[64][65];
    __shared__ float Bm[64][65];
    __shared__ float Cm[64][65];

    #pragma unroll
    for (int e = 0; e < 16; e++) {
        int idx = tid + e * 256;
        int g = idx >> 6, d = idx & 63;
        A[g][d] = tok[(size_t)bh * 4096 + idx] / (norm[bh * 64 + g] + 1e-5f);
    }
    __syncthreads();

    {
        float aq[4][4] = {}, ak[4][4] = {};
        #pragma unroll
        for (int kk = 0; kk < 64; kk++) {
            float a[4];
            #pragma unroll
            for (int i = 0; i < 4; i++) a[i] = A[ty + 16 * i][kk];
            #pragma unroll
            for (int j = 0; j < 4; j++) {
                float wq = __ldg(&Wq[(tx + 16 * j) * 64 + kk]);
                float wk = __ldg(&Wk[(tx + 16 * j) * 64 + kk]);
                #pragma unroll
                for (int i = 0; i < 4; i++) {
                    aq[i][j] += a[i] * wq;
                    ak[i][j] += a[i] * wk;
                }
            }
        }
        #pragma unroll
        for (int i = 0; i < 4; i++)
            #pragma unroll
            for (int j = 0; j < 4; j++) {
                Bm[ty + 16 * i][tx + 16 * j] = aq[i][j];
                Cm[ty + 16 * i][tx + 16 * j] = ak[i][j];
            }
    }
    __syncthreads();

    {
        float L[4][4] = {};
        #pragma unroll
        for (int kk = 0; kk < 64; kk++) {
            float a[4], bv[4];
            #pragma unroll
            for (int i = 0; i < 4; i++) a[i] = Bm[ty + 16 * i][kk];
            #pragma unroll
            for (int j = 0; j < 4; j++) bv[j] = Cm[tx + 16 * j][kk];
            #pragma unroll
            for (int i = 0; i < 4; i++)
                #pragma unroll
                for (int j = 0; j < 4; j++)
                    L[i][j] += a[i] * bv[j];
        }
        #pragma unroll
        for (int i = 0; i < 4; i++) {
            #pragma unroll
            for (int j = 0; j < 4; j++) L[i][j] *= 0.125f;
            float mx = L[i][0];
            #pragma unroll
            for (int j = 1; j < 4; j++) mx = fmaxf(mx, L[i][j]);
            #pragma unroll
            for (int o = 1; o < 16; o <<= 1)
                mx = fmaxf(mx, __shfl_xor_sync(0xffffffffu, mx, o, 16));
            float s = 0.f;
            #pragma unroll
            for (int j = 0; j < 4; j++) { L[i][j] = __expf(L[i][j] - mx); s += L[i][j]; }
            #pragma unroll
            for (int o = 1; o < 16; o <<= 1)
                s += __shfl_xor_sync(0xffffffffu, s, o, 16);
            float inv = 1.0f / s;
            #pragma unroll
            for (int j = 0; j < 4; j++)
                A[ty + 16 * i][tx + 16 * j] = L[i][j] * inv;
        }
    }
    __syncthreads();

    #pragma unroll
    for (int e = 0; e < 16; e++) {
        int idx = tid + e * 256;
        int g = idx >> 6;
        Bm[g][idx & 63] = tok[(size_t)bh * 4096 + idx] / (norm[bh * 64 + g] + 1e-5f);
    }
    __syncthreads();

    {
        float av[4][4] = {};
        #pragma unroll
        for (int kk = 0; kk < 64; kk++) {
            float a[4];
            #pragma unroll
            for (int i = 0; i < 4; i++) a[i] = Bm[ty + 16 * i][kk];
            #pragma unroll
            for (int j = 0; j < 4; j++) {
                float wv = __ldg(&Wv[(tx + 16 * j) * 64 + kk]);
                #pragma unroll
                for (int i = 0; i < 4; i++) av[i][j] += a[i] * wv;
            }
        }
        __syncthreads();
        #pragma unroll
        for (int i = 0; i < 4; i++)
            #pragma unroll
            for (int j = 0; j < 4; j++)
                Cm[ty + 16 * i][tx + 16 * j] = av[i][j];
    }
    __syncthreads();

    {
        float ao[4][4] = {};
        #pragma unroll
        for (int kk = 0; kk < 64; kk++) {
            float a[4], bv[4];
            #pragma unroll
            for (int i = 0; i < 4; i++) a[i] = A[ty + 16 * i][kk];
            #pragma unroll
            for (int j = 0; j < 4; j++) bv[j] = Cm[kk][tx + 16 * j];
            #pragma unroll
            for (int i = 0; i < 4; i++)
                #pragma unroll
                for (int j = 0; j < 4; j++)
                    ao[i][j] += a[i] * bv[j];
        }
        __syncthreads();
        #pragma unroll
        for (int i = 0; i < 4; i++)
            #pragma unroll
            for (int j = 0; j < 4; j++)
                Bm[ty + 16 * i][tx + 16 * j] = ao[i][j];
    }
    __syncthreads();

    {
        float am[4][8] = {};
        #pragma unroll
        for (int kk = 0; kk < 64; kk++) {
            float a[4];
            #pragma unroll
            for (int i = 0; i < 4; i++) a[i] = Bm[ty + 16 * i][kk];
            #pragma unroll
            for (int j = 0; j < 8; j++) {
                float wv = __ldg(&Wout[(size_t)(tx + 16 * j) * INNER + h * DH + kk]);
                #pragma unroll
                for (int i = 0; i < 4; i++) am[i][j] += a[i] * wv;
            }
        }
        #pragma unroll
        for (int i = 0; i < 4; i++) {
            int g = ty + 16 * i;
            #pragma unroll
            for (int j = 0; j < 8; j++) {
                int o = tx + 16 * j;
                float v = am[i][j];
                __nv_bfloat16 hv = __float2bfloat16(v);
                float r = v - __bfloat162float(hv);
                size_t idx = ((size_t)b * CC + o) * INNER + h * DH + g;
                Mthi[idx] = hv;
                Mtlo[idx] = __float2bfloat16(r);
            }
        }
    }
}

// ---------------- K5: fused scatter + projection, kc=32, 4 warps, 2 CTAs/SM ----------------
#define FSTAGE 32768
#define FNCHUNK 16

__device__ __forceinline__ void fin_load(
    uint32_t st,
    const __nv_bfloat16* __restrict__ Whi, const __nv_bfloat16* __restrict__ Wlo,
    const __nv_bfloat16* __restrict__ Mthi, const __nv_bfloat16* __restrict__ Mtlo,
    int it, int b, int n0, int tid)
{
    const int h  = it >> 1;
    const int g0 = (it & 1) * 32;

    #pragma unroll
    for (int j = 0; j < 8; j++) {
        int id  = tid + j * 128;
        int arr = id >> 9;              // 0:whi 1:wlo
        int l   = id & 511;
        int row = l >> 2;
        int gr  = l & 3;
        uint32_t saddr = st + arr * 8192 + sw32(row, gr);
        const __nv_bfloat16* g = (arr == 0 ? Whi : Wlo) +
            (((size_t)(b * HEADS + h) * NN) + n0 + row) * GG + g0 + gr * 8;
        cp16(saddr, g, true);
    }
    #pragma unroll
    for (int j = 0; j < 8; j++) {
        int id  = tid + j * 128;
        int arr = id >> 9;              // 0:Mthi 1:Mtlo
        int l   = id & 511;
        int row = l >> 2;
        int gr  = l & 3;
        uint32_t saddr = st + 16384 + arr * 8192 + sw32(row, gr);
        const __nv_bfloat16* g = (arr == 0 ? Mthi : Mtlo) +
            ((size_t)b * CC + row) * INNER + h * DH + g0 + gr * 8;
        cp16(saddr, g, true);
    }
}

__global__ __launch_bounds__(128, 2)
void final_mma_kernel(const __nv_bfloat16* __restrict__ Whi,
                      const __nv_bfloat16* __restrict__ Wlo,
                      const __nv_bfloat16* __restrict__ Mthi,
                      const __nv_bfloat16* __restrict__ Mtlo,
                      const float* __restrict__ bout,
                      float* __restrict__ out)
{
    extern __shared__ char smem[];           // 3 stages x 32KB

    const int pt = blockIdx.x;
    const int b  = pt >> 9;
    const int n0 = (pt & 511) * 128;

    const int tid  = threadIdx.x;            // 0..127
    const int wid  = tid >> 5;
    const int lane = tid & 31;
    const int grp  = lane >> 2;
    const int tid4 = lane & 3;
    const int wm   = wid & 1;                // 2 row-groups of 64
    const int wn   = wid >> 1;               // 2 col-groups of 64

    const int t8   = lane >> 3;
    const int r8   = lane & 7;
    const int a_roff = ((t8 & 1) << 3) + r8;
    const int a_gsel = t8 >> 1;
    const int b_roff = ((t8 >> 1) << 3) + r8;
    const int b_gsel = t8 & 1;

    float acc[4][8][4];
    #pragma unroll
    for (int i = 0; i < 4; i++)
        #pragma unroll
        for (int j = 0; j < 8; j++)
            #pragma unroll
            for (int r = 0; r < 4; r++) acc[i][j][r] = 0.f;

    uint32_t sbase = (uint32_t)__cvta_generic_to_shared(smem);

    fin_load(sbase, Whi, Wlo, Mthi, Mtlo, 0, b, n0, tid);
    asm volatile("cp.async.commit_group;\n" ::: "memory");
    fin_load(sbase + FSTAGE, Whi, Wlo, Mthi, Mtlo, 1, b, n0, tid);
    asm volatile("cp.async.commit_group;\n" ::: "memory");

    for (int it = 0; it < FNCHUNK; ++it) {
        const int cur = it % 3;
        if (it + 2 < FNCHUNK)
            fin_load(sbase + (uint32_t)((it + 2) % 3) * FSTAGE,
                     Whi, Wlo, Mthi, Mtlo, it + 2, b, n0, tid);
        asm volatile("cp.async.commit_group;\n" ::: "memory");
        asm volatile("cp.async.wait_group 2;\n" ::: "memory");
        __syncthreads();

        const uint32_t stA = sbase + (uint32_t)cur * FSTAGE;
        const uint32_t stB = stA + 16384;

        #pragma unroll
        for (int s = 0; s < 2; s++) {
            uint32_t ah[4][4], al[4][4];
            #pragma unroll
            for (int mi = 0; mi < 4; mi++) {
                int row = wm * 64 + mi * 16 + a_roff;
                int g = 2 * s + a_gsel;
                uint32_t addr = stA + sw32(row, g);
                ldsm4(ah[mi], addr);
                ldsm4(al[mi], addr + 8192);
            }
            #pragma unroll
            for (int np = 0; np < 4; np++) {
                int row = wn * 64 + np * 16 + b_roff;
                int g = 2 * s + b_gsel;
                uint32_t addr = stB + sw32(row, g);
                uint32_t bh[4], bl[4];
                ldsm4(bh, addr);
                ldsm4(bl, addr + 8192);
                #pragma unroll
                for (int mi = 0; mi < 4; mi++) {
                    mma_bf16(acc[mi][2 * np],     ah[mi][0], ah[mi][1], ah[mi][2], ah[mi][3], bh[0], bh[1]);
                    mma_bf16(acc[mi][2 * np + 1], ah[mi][0], ah[mi][1], ah[mi][2], ah[mi][3], bh[2], bh[3]);
                }
                #pragma unroll
                for (int mi = 0; mi < 4; mi++) {
                    mma_bf16(acc[mi][2 * np],     ah[mi][0], ah[mi][1], ah[mi][2], ah[mi][3], bl[0], bl[1]);
                    mma_bf16(acc[mi][2 * np + 1], ah[mi][0], ah[mi][1], ah[mi][2], ah[mi][3], bl[2], bl[3]);
                }
                #pragma unroll
                for (int mi = 0; mi < 4; mi++) {
                    mma_bf16(acc[mi][2 * np],     al[mi][0], al[mi][1], al[mi][2], al[mi][3], bh[0], bh[1]);
                    mma_bf16(acc[mi][2 * np + 1], al[mi][0], al[mi][1], al[mi][2], al[mi][3], bh[2], bh[3]);
                }
            }
        }
        __syncthreads();
    }

    #pragma unroll
    for (int mi = 0; mi < 4; mi++) {
        int row = wm * 64 + mi * 16 + grp;
        int n  = n0 + row;
        #pragma unroll
        for (int ni = 0; ni < 8; ni++) {
            int oc = wn * 64 + ni * 8 + tid4 * 2;
            float b0v = bout[oc], b1v = bout[oc + 1];
            size_t base0 = ((size_t)b * NN + n) * CC + oc;
            out[base0]     = acc[mi][ni][0] + b0v;
            out[base0 + 1] = acc[mi][ni][1] + b1v;
            size_t base1 = ((size_t)b * NN + n + 8) * CC + oc;
            out[base1]     = acc[mi][ni][2] + b0v;
            out[base1 + 1] = acc[mi][ni][3] + b1v;
        }
    }
}

// ---------------- launch ----------------
extern "C" void kernel_launch(void* const* d_in, const int* in_sizes, int n_in,
                              void* d_out, int out_size) {
    const float* x     = (const float*)d_in[0];
    const float* Wfx   = (const float*)d_in[1];
    const float* bfx   = (const float*)d_in[2];
    const float* Wx    = (const float*)d_in[3];
    const float* bx    = (const float*)d_in[4];
    const float* Wsl   = (const float*)d_in[5];
    const float* bsl   = (const float*)d_in[6];
    const float* temp  = (const float*)d_in[7];
    const float* Wq    = (const float*)d_in[8];
    const float* Wk    = (const float*)d_in[9];
    const float* Wv    = (const float*)d_in[10];
    const float* Wout  = (const float*)d_in[11];
    const float* bout  = (const float*)d_in[12];
    float* out = (float*)d_out;

    float *p_tokp, *p_normp, *p_tok, *p_norm, *p_lb;
    __nv_bfloat16 *p_xhi, *p_xlo, *p_whi, *p_wlo;
    __nv_bfloat16 *p_fxhi;
    __nv_bfloat16 *p_swhi, *p_swlo, *p_Mthi, *p_Mtlo;
    cudaGetSymbolAddress((void**)&p_tokp, g_tokp);
    cudaGetSymbolAddress((void**)&p_normp, g_normp);
    cudaGetSymbolAddress((void**)&p_tok, g_tok);
    cudaGetSymbolAddress((void**)&p_norm, g_norm);
    cudaGetSymbolAddress((void**)&p_lb, g_lbias);
    cudaGetSymbolAddress((void**)&p_xhi, g_xhi);
    cudaGetSymbolAddress((void**)&p_xlo, g_xlo);
    cudaGetSymbolAddress((void**)&p_whi, g_whi);
    cudaGetSymbolAddress((void**)&p_wlo, g_wlo);
    cudaGetSymbolAddress((void**)&p_fxhi, g_fxhi);
    cudaGetSymbolAddress((void**)&p_swhi, g_swhi);
    cudaGetSymbolAddress((void**)&p_swlo, g_swlo);
    cudaGetSymbolAddress((void**)&p_Mthi, g_Mthi);
    cudaGetSymbolAddress((void**)&p_Mtlo, g_Mtlo);

    static bool attr_set = false;
    if (!attr_set) {
        cudaFuncSetAttribute(conv_mma_kernel,
                             cudaFuncAttributeMaxDynamicSharedMemorySize, 3 * CSTAGE);
        cudaFuncSetAttribute(final_mma_kernel,
                             cudaFuncAttributeMaxDynamicSharedMemorySize, 3 * FSTAGE);
        attr_set = true;
    }

    dim3 blk(16, 16);

    // 0. staging (3 launches; conv is launch #4 for ncu visibility)
    split_x_kernel<<<(BB * NN * CC) / 1024, 256>>>(
        (const float4*)x, (uint2*)p_xhi, (uint2*)p_xlo);
    split_w_kernel<<<(512 * KTOT) / 256, 256>>>(Wfx, p_whi, p_wlo);
    combine_w_kernel<<<dim3(512, 10), 128>>>(Wx, Wsl, bx, bsl, temp, p_whi, p_wlo, p_lb);

    // 1. fused conv (launch #4): 128x128 tiles, 4 warps, 2 CTAs/SM, 3-stage
    conv_mma_kernel<<<dim3(8, 512, BB), 128, 3 * CSTAGE>>>(
        p_xhi, p_xlo, p_whi, p_wlo, bfx, p_lb, p_fxhi, p_swhi, p_swlo);

    // 2. slice token reduction on tensor cores + split reduce
    token_mma_kernel<<<dim3(SPLITS, BB * HEADS), 128>>>(
        p_swhi, p_swlo, p_fxhi, p_tokp, p_normp);
    split_reduce_kernel<<<260, 256>>>(p_tokp, p_normp, p_tok, p_norm);

    // 3. tiny attention + fused Wout fold -> Mt (bf16 hi/lo)
    attn_kernel<<<BB * HEADS, blk>>>(p_tok, p_norm, Wq, Wk, Wv, Wout, p_Mthi, p_Mtlo);

    // 4. fused scatter + projection: kc=32, 4 warps, 2 CTAs/SM, 3-stage
    final_mma_kernel<<<1024, 128, 3 * FSTAGE>>>(p_swhi, p_swlo, p_Mthi, p_Mtlo, bout, out);
}

// round 17
// speedup vs baseline: 1.1353x; 1.0095x over previous
#include <cuda_runtime.h>
#include <cuda_bf16.h>
#include <math.h>
#include <stdint.h>

// Problem constants
#define BB 2
#define HH 256
#define WW 256
#define NN 65536          // H*W
#define CC 128
#define HEADS 8
#define DH 64             // dim_head
#define GG 64             // SLICE
#define INNER 512         // HEADS*DH
#define SPLITS 32         // split-K for token reduction
#define CHUNK 2048        // tokens per split (NN/SPLITS)
#define KTOT 1152         // 9 taps * 128 channels

// ---------------- device scratch (static, no allocs) ----------------
__device__ float g_tokp[(size_t)SPLITS * BB * HEADS * GG * DH];
__device__ float g_normp[(size_t)SPLITS * BB * HEADS * GG];
__device__ float g_tok [(size_t)BB * HEADS * GG * DH];
__device__ float g_norm[(size_t)BB * HEADS * GG];
__device__ float g_lbias[INNER];                     // (bx·Wslice + bslice)/temp

// fx_mid as single bf16  [b][n][inner]
__device__ __align__(16) __nv_bfloat16 g_fxhi[(size_t)BB * NN * INNER];
// slice weights as bf16 hi/lo pair  [bh][n][g]
__device__ __align__(16) __nv_bfloat16 g_swhi[(size_t)BB * HEADS * NN * GG];
__device__ __align__(16) __nv_bfloat16 g_swlo[(size_t)BB * HEADS * NN * GG];
// Mt = (out_slice · Wout^T) transposed: [b][o][h*64+g], bf16 hi/lo
__device__ __align__(16) __nv_bfloat16 g_Mthi[(size_t)BB * CC * INNER];
__device__ __align__(16) __nv_bfloat16 g_Mtlo[(size_t)BB * CC * INNER];

// bf16 3-split staging for conv
__device__ __align__(16) __nv_bfloat16 g_xhi[(size_t)BB * NN * CC];
__device__ __align__(16) __nv_bfloat16 g_xlo[(size_t)BB * NN * CC];
// rows 0..511: Wfx cols; rows 512..1023: combined logit weights (Wx·Wslice/temp)
__device__ __align__(16) __nv_bfloat16 g_whi[(size_t)1024 * KTOT];
__device__ __align__(16) __nv_bfloat16 g_wlo[(size_t)1024 * KTOT];

// ---------------- prep kernels ----------------
// vectorized 4x: float4 in, packed 4xbf16 (uint2) out
__global__ void split_x_kernel(const float4* __restrict__ x,
                               uint2* __restrict__ xhi,
                               uint2* __restrict__ xlo) {
    size_t i = (size_t)blockIdx.x * 256 + threadIdx.x;
    float4 f = x[i];
    union { __nv_bfloat16 hb[4]; uint2 u; } Uh, Ul;
    Uh.hb[0] = __float2bfloat16(f.x);
    Uh.hb[1] = __float2bfloat16(f.y);
    Uh.hb[2] = __float2bfloat16(f.z);
    Uh.hb[3] = __float2bfloat16(f.w);
    Ul.hb[0] = __float2bfloat16(f.x - __bfloat162float(Uh.hb[0]));
    Ul.hb[1] = __float2bfloat16(f.y - __bfloat162float(Uh.hb[1]));
    Ul.hb[2] = __float2bfloat16(f.z - __bfloat162float(Uh.hb[2]));
    Ul.hb[3] = __float2bfloat16(f.w - __bfloat162float(Uh.hb[3]));
    xhi[i] = Uh.u;
    xlo[i] = Ul.u;
}

// Wfx -> rows 0..511 of g_whi/g_wlo, transposed [oc][k], via smem tile transpose
__global__ void split_w_kernel(const float* __restrict__ Wfx,
                               __nv_bfloat16* __restrict__ whi,
                               __nv_bfloat16* __restrict__ wlo) {
    __shared__ float tile[32][33];
    const int kb = blockIdx.x * 32;   // k base   (36 blocks)
    const int ob = blockIdx.y * 32;   // oc base  (16 blocks)
    const int tx = threadIdx.x;       // 0..31
    const int ty = threadIdx.y;       // 0..7
    #pragma unroll
    for (int r = 0; r < 4; r++) {
        int k = kb + ty + 8 * r;
        tile[ty + 8 * r][tx] = Wfx[(size_t)k * 512 + ob + tx];  // coalesced read
    }
    __syncthreads();
    #pragma unroll
    for (int r = 0; r < 4; r++) {
        int oc = ob + ty + 8 * r;
        int k  = kb + tx;
        float f = tile[tx][ty + 8 * r];
        __nv_bfloat16 h = __float2bfloat16(f);
        size_t o = (size_t)oc * KTOT + k;                        // coalesced write
        whi[o] = h;
        wlo[o] = __float2bfloat16(f - __bfloat162float(h));
    }
}

// blockIdx.x = h (0..7); blockIdx.y = yk (0..8: k-blocks of 128; 9: lbias)
__global__ void combine_w_kernel(const float* __restrict__ Wx,
                                 const float* __restrict__ Wsl,
                                 const float* __restrict__ bx,
                                 const float* __restrict__ bsl,
                                 const float* __restrict__ temp,
                                 __nv_bfloat16* __restrict__ whi,
                                 __nv_bfloat16* __restrict__ wlo,
                                 float* __restrict__ lb) {
    __shared__ float ws[64][65];
    const int h   = blockIdx.x;
    const int yk  = blockIdx.y;
    const int tid = threadIdx.x;         // 128
    for (int i = tid; i < 4096; i += 128)
        ws[i >> 6][i & 63] = Wsl[i];
    __syncthreads();
    float t = fminf(fmaxf(temp[h], 0.1f), 5.0f);
    float invt = 1.0f / t;

    if (yk == 9) {
        if (tid < 64) {
            float s = bsl[tid];
            #pragma unroll 8
            for (int d = 0; d < 64; d++) s += bx[h * 64 + d] * ws[tid][d];
            lb[h * 64 + tid] = s * invt;
        }
        return;
    }

    const int k = yk * 128 + tid;        // 0..1151
    float xr[64];
    const float* wr = Wx + (size_t)k * 512 + h * 64;
    #pragma unroll
    for (int d = 0; d < 64; d++) xr[d] = wr[d];

    #pragma unroll 4
    for (int g = 0; g < 64; g++) {
        float s = 0.f;
        #pragma unroll 8
        for (int d = 0; d < 64; d++) s += xr[d] * ws[g][d];
        s *= invt;
        __nv_bfloat16 hv = __float2bfloat16(s);
        size_t o = (size_t)(512 + h * 64 + g) * KTOT + k;   // coalesced over tid
        whi[o] = hv;
        wlo[o] = __float2bfloat16(s - __bfloat162float(hv));
    }
}

// ---------------- shared MMA plumbing ----------------
__device__ __forceinline__ void cp16(uint32_t saddr, const void* g, bool valid) {
    int sz = valid ? 16 : 0;
    asm volatile("cp.async.cg.shared.global [%0], [%1], 16, %2;\n"
                 :: "r"(saddr), "l"(g), "r"(sz));
}

__device__ __forceinline__ void mma_bf16(float c[4], uint32_t a0, uint32_t a1,
                                         uint32_t a2, uint32_t a3,
                                         uint32_t b0, uint32_t b1) {
    asm volatile(
        "mma.sync.aligned.m16n8k16.row.col.f32.bf16.bf16.f32 "
        "{%0,%1,%2,%3}, {%4,%5,%6,%7}, {%8,%9}, {%0,%1,%2,%3};"
        : "+f"(c[0]), "+f"(c[1]), "+f"(c[2]), "+f"(c[3])
        : "r"(a0), "r"(a1), "r"(a2), "r"(a3), "r"(b0), "r"(b1));
}

__device__ __forceinline__ void ldsm4(uint32_t r[4], uint32_t addr) {
    asm volatile("ldmatrix.sync.aligned.m8n8.x4.shared.b16 {%0,%1,%2,%3}, [%4];"
                 : "=r"(r[0]), "=r"(r[1]), "=r"(r[2]), "=r"(r[3]) : "r"(addr));
}

__device__ __forceinline__ void ldsm4t(uint32_t r[4], uint32_t addr) {
    asm volatile("ldmatrix.sync.aligned.m8n8.x4.trans.shared.b16 {%0,%1,%2,%3}, [%4];"
                 : "=r"(r[0]), "=r"(r[1]), "=r"(r[2]), "=r"(r[3]) : "r"(addr));
}

// packed kc=32 tile: 128 logical rows x 32 bf16, two logical rows per 128B phys row.
__device__ __forceinline__ uint32_t sw32(int row, int gr) {
    return (uint32_t)(row >> 1) * 128 +
           (uint32_t)(((gr | ((row & 1) << 2)) ^ ((row >> 1) & 7)) << 4);
}

// ---------------- conv: implicit GEMM 128x128, kc=32, 4 warps, 2 CTAs/SM ----------------
#define CSTAGE 32768
#define NCHUNK 36

__device__ __forceinline__ void conv_load(
    uint32_t st,
    const __nv_bfloat16* __restrict__ Xhi, const __nv_bfloat16* __restrict__ Xlo,
    const __nv_bfloat16* __restrict__ Whi, const __nv_bfloat16* __restrict__ Wlo,
    int it, int b, int hrow, int w0, int ocb, int tid)
{
    const int kg  = it * 32;
    const int tap = kg >> 7;
    const int dy = tap / 3 - 1, dx = tap % 3 - 1;
    const int c0 = kg & 127;            // 0/32/64/96
    const int hp = hrow + dy;
    const bool hok = (hp >= 0) && (hp < HH);
    const int hpc = hok ? hp : 0;

    #pragma unroll
    for (int j = 0; j < 8; j++) {
        int id  = tid + j * 128;
        int arr = id >> 9;              // 0:Ahi 1:Alo
        int l   = id & 511;
        int row = l >> 2;
        int gr  = l & 3;
        uint32_t saddr = st + arr * 8192 + sw32(row, gr);
        int wp = w0 + row + dx;
        bool valid = hok && (wp >= 0) && (wp < WW);
        int wpc = valid ? wp : 0;
        const __nv_bfloat16* g = (arr == 0 ? Xhi : Xlo) +
            (((size_t)b * NN + (size_t)hpc * WW + wpc) * CC + c0 + gr * 8);
        cp16(saddr, g, valid);
    }
    #pragma unroll
    for (int j = 0; j < 8; j++) {
        int id  = tid + j * 128;
        int arr = id >> 9;              // 0:Bhi 1:Blo
        int l   = id & 511;
        int row = l >> 2;
        int gr  = l & 3;
        uint32_t saddr = st + 16384 + arr * 8192 + sw32(row, gr);
        const __nv_bfloat16* g = (arr == 0 ? Whi : Wlo) +
            ((size_t)(ocb * 128 + row) * KTOT + kg + gr * 8);
        cp16(saddr, g, true);
    }
}

__global__ __launch_bounds__(128, 2)
void conv_mma_kernel(const __nv_bfloat16* __restrict__ Xhi,
                     const __nv_bfloat16* __restrict__ Xlo,
                     const __nv_bfloat16* __restrict__ Whi,
                     const __nv_bfloat16* __restrict__ Wlo,
                     const float* __restrict__ bfx,
                     const float* __restrict__ lbias,
                     __nv_bfloat16* __restrict__ fxhi,
                     __nv_bfloat16* __restrict__ swhi,
                     __nv_bfloat16* __restrict__ swlo)
{
    extern __shared__ char smem[];           // 3 stages x 32KB

    const int ocb = blockIdx.x;              // 0..7
    const int pt  = blockIdx.y;              // 0..511
    const int b   = blockIdx.z;
    const int n0  = pt * 128;
    const int hrow = n0 >> 8;
    const int w0   = n0 & 255;

    const int tid  = threadIdx.x;            // 0..127
    const int wid  = tid >> 5;               // 0..3
    const int lane = tid & 31;
    const int grp  = lane >> 2;
    const int tid4 = lane & 3;
    const int wm   = wid & 1;                // 2 row-groups of 64
    const int wn   = wid >> 1;               // 2 col-groups of 64

    const int t8   = lane >> 3;
    const int r8   = lane & 7;
    const int a_roff = ((t8 & 1) << 3) + r8;
    const int a_gsel = t8 >> 1;
    const int b_roff = ((t8 >> 1) << 3) + r8;
    const int b_gsel = t8 & 1;

    float acc[4][8][4];
    #pragma unroll
    for (int i = 0; i < 4; i++)
        #pragma unroll
        for (int j = 0; j < 8; j++)
            #pragma unroll
            for (int r = 0; r < 4; r++) acc[i][j][r] = 0.f;

    uint32_t sbase = (uint32_t)__cvta_generic_to_shared(smem);

    conv_load(sbase, Xhi, Xlo, Whi, Wlo, 0, b, hrow, w0, ocb, tid);
    asm volatile("cp.async.commit_group;\n" ::: "memory");
    conv_load(sbase + CSTAGE, Xhi, Xlo, Whi, Wlo, 1, b, hrow, w0, ocb, tid);
    asm volatile("cp.async.commit_group;\n" ::: "memory");

    for (int it = 0; it < NCHUNK; ++it) {
        const int cur = it % 3;
        if (it + 2 < NCHUNK)
            conv_load(sbase + (uint32_t)((it + 2) % 3) * CSTAGE,
                      Xhi, Xlo, Whi, Wlo, it + 2, b, hrow, w0, ocb, tid);
        asm volatile("cp.async.commit_group;\n" ::: "memory");
        asm volatile("cp.async.wait_group 2;\n" ::: "memory");
        __syncthreads();

        const uint32_t stA = sbase + (uint32_t)cur * CSTAGE;
        const uint32_t stB = stA + 16384;

        #pragma unroll
        for (int s = 0; s < 2; s++) {
            uint32_t ah[4][4], al[4][4];
            #pragma unroll
            for (int mi = 0; mi < 4; mi++) {
                int row = wm * 64 + mi * 16 + a_roff;
                int g = 2 * s + a_gsel;
                uint32_t addr = stA + sw32(row, g);
                ldsm4(ah[mi], addr);
                ldsm4(al[mi], addr + 8192);
            }
            #pragma unroll
            for (int np = 0; np < 4; np++) {
                int row = wn * 64 + np * 16 + b_roff;
                int g = 2 * s + b_gsel;
                uint32_t addr = stB + sw32(row, g);
                uint32_t bh[4], bl[4];
                ldsm4(bh, addr);
                ldsm4(bl, addr + 8192);
                #pragma unroll
                for (int mi = 0; mi < 4; mi++) {
                    mma_bf16(acc[mi][2 * np],     ah[mi][0], ah[mi][1], ah[mi][2], ah[mi][3], bh[0], bh[1]);
                    mma_bf16(acc[mi][2 * np + 1], ah[mi][0], ah[mi][1], ah[mi][2], ah[mi][3], bh[2], bh[3]);
                }
                #pragma unroll
                for (int mi = 0; mi < 4; mi++) {
                    mma_bf16(acc[mi][2 * np],     ah[mi][0], ah[mi][1], ah[mi][2], ah[mi][3], bl[0], bl[1]);
                    mma_bf16(acc[mi][2 * np + 1], ah[mi][0], ah[mi][1], ah[mi][2], ah[mi][3], bl[2], bl[3]);
                }
                #pragma unroll
                for (int mi = 0; mi < 4; mi++) {
                    mma_bf16(acc[mi][2 * np],     al[mi][0], al[mi][1], al[mi][2], al[mi][3], bh[0], bh[1]);
                    mma_bf16(acc[mi][2 * np + 1], al[mi][0], al[mi][1], al[mi][2], al[mi][3], bh[2], bh[3]);
                }
            }
        }
        __syncthreads();
    }

    if (ocb < 4) {
        const int ocbase = ocb * 128;
        #pragma unroll
        for (int mi = 0; mi < 4; mi++) {
            int row = wm * 64 + mi * 16 + grp;
            int n  = n0 + row;
            #pragma unroll
            for (int ni = 0; ni < 8; ni++) {
                int col = wn * 64 + ni * 8 + tid4 * 2;
                int oc  = ocbase + col;
                float b0v = bfx[oc], b1v = bfx[oc + 1];
                __nv_bfloat162 p0;
                p0.x = __float2bfloat16(acc[mi][ni][0] + b0v);
                p0.y = __float2bfloat16(acc[mi][ni][1] + b1v);
                __nv_bfloat162 p1;
                p1.x = __float2bfloat16(acc[mi][ni][2] + b0v);
                p1.y = __float2bfloat16(acc[mi][ni][3] + b1v);
                *(__nv_bfloat162*)(fxhi + ((size_t)b * NN + n) * INNER + oc) = p0;
                *(__nv_bfloat162*)(fxhi + ((size_t)b * NN + n + 8) * INNER + oc) = p1;
            }
        }
    } else {
        float* sred = (float*)smem;          // [128][132]
        #pragma unroll
        for (int mi = 0; mi < 4; mi++) {
            int row = wm * 64 + mi * 16 + grp;
            #pragma unroll
            for (int ni = 0; ni < 8; ni++) {
                int col = wn * 64 + ni * 8 + tid4 * 2;
                sred[row * 132 + col]           = acc[mi][ni][0];
                sred[row * 132 + col + 1]       = acc[mi][ni][1];
                sred[(row + 8) * 132 + col]     = acc[mi][ni][2];
                sred[(row + 8) * 132 + col + 1] = acc[mi][ni][3];
            }
        }
        __syncthreads();

        #pragma unroll
        for (int pass = 0; pass < 2; pass++) {
            int tsk = tid + pass * 128;      // 0..255
            int row  = tsk >> 1;
            int hloc = tsk & 1;
            int h = (ocb - 4) * 2 + hloc;
            int n = n0 + row;
            const float* lb = lbias + h * 64;
            float* sr = sred + row * 132 + hloc * 64;

            float mx = -1e30f;
            #pragma unroll 8
            for (int g = 0; g < 64; g++) mx = fmaxf(mx, sr[g] + lb[g]);
            float ssum = 0.f;
            #pragma unroll 8
            for (int g = 0; g < 64; g++) {
                float e = __expf(sr[g] + lb[g] - mx);
                ssum += e;
                sr[g] = e;
            }
            float inv = 1.0f / ssum;

            size_t base = ((size_t)(b * HEADS + h) * NN + n) * GG;
            #pragma unroll
            for (int c = 0; c < 8; c++) {
                union { __nv_bfloat16 hb[8]; uint4 u; } Uh, Ul;
                #pragma unroll
                for (int e = 0; e < 8; e++) {
                    float v = sr[c * 8 + e] * inv;
                    __nv_bfloat16 hv = __float2bfloat16(v);
                    Uh.hb[e] = hv;
                    Ul.hb[e] = __float2bfloat16(v - __bfloat162float(hv));
                }
                ((uint4*)(swhi + base))[c] = Uh.u;
                ((uint4*)(swlo + base))[c] = Ul.u;
            }
        }
    }
}

// ---------------- K3: token reduction on tensor cores (fx single bf16) ----------------
__global__ __launch_bounds__(128)
void token_mma_kernel(const __nv_bfloat16* __restrict__ whi,
                      const __nv_bfloat16* __restrict__ wlo,
                      const __nv_bfloat16* __restrict__ fx,
                      float* __restrict__ tokp,
                      float* __restrict__ normp)
{
    __shared__ __align__(16) char smem[2 * 6144];

    const int bh = blockIdx.y;
    const int b = bh >> 3, h = bh & 7;
    const int split = blockIdx.x;
    const int nbase = split * CHUNK;

    const int tid  = threadIdx.x;
    const int wid  = tid >> 5;          // 0..3: g-strip wid*16
    const int lane = tid & 31;
    const int grp  = lane >> 2;
    const int tid4 = lane & 3;
    const int t8   = lane >> 3;
    const int r8   = lane & 7;
    const int lrow = r8 + ((t8 >> 1) << 3);   // 0..15
    const int lgr  = t8 & 1;

    const uint32_t ONES = 0x3F803F80u;  // bf16(1.0) x2

    float acc[8][4];
    #pragma unroll
    for (int j = 0; j < 8; j++)
        #pragma unroll
        for (int r = 0; r < 4; r++) acc[j][r] = 0.f;
    float accn[4] = {};

    uint32_t sbase = (uint32_t)__cvta_generic_to_shared(smem);

    auto load = [&](uint32_t st, int t0) {
        #pragma unroll
        for (int j = 0; j < 3; j++) {
            int id  = tid + j * 128;
            int arr = id >> 7;          // 0:whi 1:wlo 2:fx
            int l   = id & 127;
            int row = l >> 3;
            int gr  = l & 7;
            uint32_t saddr = st + arr * 2048 + row * 128 + ((gr ^ (row & 7)) << 4);
            int n = nbase + t0 + row;
            const __nv_bfloat16* g;
            if (arr < 2) {
                g = (arr == 0 ? whi : wlo) + ((size_t)bh * NN + n) * GG + gr * 8;
            } else {
                g = fx + ((size_t)b * NN + n) * INNER + h * DH + gr * 8;
            }
            cp16(saddr, g, true);
        }
    };

    load(sbase, 0);
    asm volatile("cp.async.commit_group;\n" ::: "memory");

    const int NIT = CHUNK / 16;         // 128
    for (int it = 0; it < NIT; ++it) {
        const int cur = it & 1;
        if (it + 1 < NIT) {
            load(sbase + (uint32_t)(1 - cur) * 6144, (it + 1) * 16);
            asm volatile("cp.async.commit_group;\n" ::: "memory");
            asm volatile("cp.async.wait_group 1;\n" ::: "memory");
        } else {
            asm volatile("cp.async.wait_group 0;\n" ::: "memory");
        }
        __syncthreads();

        const uint32_t st = sbase + (uint32_t)cur * 6144;

        uint32_t awh[4], awl[4];
        {
            int gr = wid * 2 + lgr;
            uint32_t addr = st + lrow * 128 + ((gr ^ (lrow & 7)) << 4);
            ldsm4t(awh, addr);
            ldsm4t(awl, addr + 2048);
        }
        mma_bf16(accn, awh[0], awh[1], awh[2], awh[3], ONES, ONES);
        mma_bf16(accn, awl[0], awl[1], awl[2], awl[3], ONES, ONES);

        #pragma unroll
        for (int j = 0; j < 4; j++) {
            int gr = j * 2 + lgr;
            uint32_t addr = st + 4096 + lrow * 128 + ((gr ^ (lrow & 7)) << 4);
            uint32_t bf[4];
            ldsm4t(bf, addr);
            mma_bf16(acc[2 * j],     awh[0], awh[1], awh[2], awh[3], bf[0], bf[2]);
            mma_bf16(acc[2 * j + 1], awh[0], awh[1], awh[2], awh[3], bf[1], bf[3]);
            mma_bf16(acc[2 * j],     awl[0], awl[1], awl[2], awl[3], bf[0], bf[2]);
            mma_bf16(acc[2 * j + 1], awl[0], awl[1], awl[2], awl[3], bf[1], bf[3]);
        }
        __syncthreads();
    }

    const size_t base = ((size_t)split * (BB * HEADS) + bh) * (GG * DH);
    const int g0 = wid * 16 + grp;
    #pragma unroll
    for (int nf = 0; nf < 8; nf++) {
        int d = (nf >> 1) * 16 + (nf & 1) * 8 + tid4 * 2;
        tokp[base + (size_t)g0 * DH + d]           = acc[nf][0];
        tokp[base + (size_t)g0 * DH + d + 1]       = acc[nf][1];
        tokp[base + (size_t)(g0 + 8) * DH + d]     = acc[nf][2];
        tokp[base + (size_t)(g0 + 8) * DH + d + 1] = acc[nf][3];
    }
    if (tid4 == 0) {
        size_t nb = ((size_t)split * (BB * HEADS) + bh) * GG;
        normp[nb + g0]     = accn[0];
        normp[nb + g0 + 8] = accn[2];
    }
}

// ---------------- K3b: deterministic split reduction ----------------
__global__ void split_reduce_kernel(const float* __restrict__ tokp,
                                    const float* __restrict__ normp,
                                    float* __restrict__ tok,
                                    float* __restrict__ norm) {
    const int blk = blockIdx.x;
    const int tid = threadIdx.x;
    if (blk < 256) {
        int idx = blk * 256 + tid;
        float s = 0.f;
        #pragma unroll 8
        for (int sp = 0; sp < SPLITS; sp++)
            s += tokp[(size_t)sp * 65536 + idx];
        tok[idx] = s;
    } else {
        int idx = (blk - 256) * 256 + tid;
        float s = 0.f;
        #pragma unroll 8
        for (int sp = 0; sp < SPLITS; sp++)
            s += normp[(size_t)sp * 1024 + idx];
        norm[idx] = s;
    }
}

// ---------------- K4: tiny attention per (b,h), emits Mt bf16 hi/lo ----------------
__global__ void attn_kernel(const float* __restrict__ tok,
                            const float* __restrict__ norm,
                            const float* __restrict__ Wq,
                            const float* __restrict__ Wk,
                            const float* __restrict__ Wv,
                            const float* __restrict__ Wout,
                            __nv_bfloat16* __restrict__ Mthi,
                            __nv_bfloat16* __restrict__ Mtlo) {
    const int bh = blockIdx.x;
    const int b = bh >> 3, h = bh & 7;
    const int tx = threadIdx.x, ty = threadIdx.y;
    const int tid = ty * 16 + tx;

    __shared__ float A[64][65];
    __shared__ float Bm[64][65];
    __shared__ float Cm[64][65];

    #pragma unroll
    for (int e = 0; e < 16; e++) {
        int idx = tid + e * 256;
        int g = idx >> 6, d = idx & 63;
        A[g][d] = tok[(size_t)bh * 4096 + idx] / (norm[bh * 64 + g] + 1e-5f);
    }
    __syncthreads();

    {
        float aq[4][4] = {}, ak[4][4] = {};
        #pragma unroll
        for (int kk = 0; kk < 64; kk++) {
            float a[4];
            #pragma unroll
            for (int i = 0; i < 4; i++) a[i] = A[ty + 16 * i][kk];
            #pragma unroll
            for (int j = 0; j < 4; j++) {
                float wq = __ldg(&Wq[(tx + 16 * j) * 64 + kk]);
                float wk = __ldg(&Wk[(tx + 16 * j) * 64 + kk]);
                #pragma unroll
                for (int i = 0; i < 4; i++) {
                    aq[i][j] += a[i] * wq;
                    ak[i][j] += a[i] * wk;
                }
            }
        }
        #pragma unroll
        for (int i = 0; i < 4; i++)
            #pragma unroll
            for (int j = 0; j < 4; j++) {
                Bm[ty + 16 * i][tx + 16 * j] = aq[i][j];
                Cm[ty + 16 * i][tx + 16 * j] = ak[i][j];
            }
    }
    __syncthreads();

    {
        float L[4][4] = {};
        #pragma unroll
        for (int kk = 0; kk < 64; kk++) {
            float a[4], bv[4];
            #pragma unroll
            for (int i = 0; i < 4; i++) a[i] = Bm[ty + 16 * i][kk];
            #pragma unroll
            for (int j = 0; j < 4; j++) bv[j] = Cm[tx + 16 * j][kk];
            #pragma unroll
            for (int i = 0; i < 4; i++)
                #pragma unroll
                for (int j = 0; j < 4; j++)
                    L[i][j] += a[i] * bv[j];
        }
        #pragma unroll
        for (int i = 0; i < 4; i++) {
            #pragma unroll
            for (int j = 0; j < 4; j++) L[i][j] *= 0.125f;
            float mx = L[i][0];
            #pragma unroll
            for (int j = 1; j < 4; j++) mx = fmaxf(mx, L[i][j]);
            #pragma unroll
            for (int o = 1; o < 16; o <<= 1)
                mx = fmaxf(mx, __shfl_xor_sync(0xffffffffu, mx, o, 16));
            float s = 0.f;
            #pragma unroll
            for (int j = 0; j < 4; j++) { L[i][j] = __expf(L[i][j] - mx); s += L[i][j]; }
            #pragma unroll
            for (int o = 1; o < 16; o <<= 1)
                s += __shfl_xor_sync(0xffffffffu, s, o, 16);
            float inv = 1.0f / s;
            #pragma unroll
            for (int j = 0; j < 4; j++)
                A[ty + 16 * i][tx + 16 * j] = L[i][j] * inv;
        }
    }
    __syncthreads();

    #pragma unroll
    for (int e = 0; e < 16; e++) {
        int idx = tid + e * 256;
        int g = idx >> 6;
        Bm[g][idx & 63] = tok[(size_t)bh * 4096 + idx] / (norm[bh * 64 + g] + 1e-5f);
    }
    __syncthreads();

    {
        float av[4][4] = {};
        #pragma unroll
        for (int kk = 0; kk < 64; kk++) {
            float a[4];
            #pragma unroll
            for (int i = 0; i < 4; i++) a[i] = Bm[ty + 16 * i][kk];
            #pragma unroll
            for (int j = 0; j < 4; j++) {
                float wv = __ldg(&Wv[(tx + 16 * j) * 64 + kk]);
                #pragma unroll
                for (int i = 0; i < 4; i++) av[i][j] += a[i] * wv;
            }
        }
        __syncthreads();
        #pragma unroll
        for (int i = 0; i < 4; i++)
            #pragma unroll
            for (int j = 0; j < 4; j++)
                Cm[ty + 16 * i][tx + 16 * j] = av[i][j];
    }
    __syncthreads();

    {
        float ao[4][4] = {};
        #pragma unroll
        for (int kk = 0; kk < 64; kk++) {
            float a[4], bv[4];
            #pragma unroll
            for (int i = 0; i < 4; i++) a[i] = A[ty + 16 * i][kk];
            #pragma unroll
            for (int j = 0; j < 4; j++) bv[j] = Cm[kk][tx + 16 * j];
            #pragma unroll
            for (int i = 0; i < 4; i++)
                #pragma unroll
                for (int j = 0; j < 4; j++)
                    ao[i][j] += a[i] * bv[j];
        }
        __syncthreads();
        #pragma unroll
        for (int i = 0; i < 4; i++)
            #pragma unroll
            for (int j = 0; j < 4; j++)
                Bm[ty + 16 * i][tx + 16 * j] = ao[i][j];
    }
    __syncthreads();

    {
        float am[4][8] = {};
        #pragma unroll
        for (int kk = 0; kk < 64; kk++) {
            float a[4];
            #pragma unroll
            for (int i = 0; i < 4; i++) a[i] = Bm[ty + 16 * i][kk];
            #pragma unroll
            for (int j = 0; j < 8; j++) {
                float wv = __ldg(&Wout[(size_t)(tx + 16 * j) * INNER + h * DH + kk]);
                #pragma unroll
                for (int i = 0; i < 4; i++) am[i][j] += a[i] * wv;
            }
        }
        #pragma unroll
        for (int i = 0; i < 4; i++) {
            int g = ty + 16 * i;
            #pragma unroll
            for (int j = 0; j < 8; j++) {
                int o = tx + 16 * j;
                float v = am[i][j];
                __nv_bfloat16 hv = __float2bfloat16(v);
                float r = v - __bfloat162float(hv);
                size_t idx = ((size_t)b * CC + o) * INNER + h * DH + g;
                Mthi[idx] = hv;
                Mtlo[idx] = __float2bfloat16(r);
            }
        }
    }
}

// ---------------- K5: fused scatter + projection, kc=32, 4 warps, 2 CTAs/SM ----------------
#define FSTAGE 32768
#define FNCHUNK 16

__device__ __forceinline__ void fin_load(
    uint32_t st,
    const __nv_bfloat16* __restrict__ Whi, const __nv_bfloat16* __restrict__ Wlo,
    const __nv_bfloat16* __restrict__ Mthi, const __nv_bfloat16* __restrict__ Mtlo,
    int it, int b, int n0, int tid)
{
    const int h  = it >> 1;
    const int g0 = (it & 1) * 32;

    #pragma unroll
    for (int j = 0; j < 8; j++) {
        int id  = tid + j * 128;
        int arr = id >> 9;              // 0:whi 1:wlo
        int l   = id & 511;
        int row = l >> 2;
        int gr  = l & 3;
        uint32_t saddr = st + arr * 8192 + sw32(row, gr);
        const __nv_bfloat16* g = (arr == 0 ? Whi : Wlo) +
            (((size_t)(b * HEADS + h) * NN) + n0 + row) * GG + g0 + gr * 8;
        cp16(saddr, g, true);
    }
    #pragma unroll
    for (int j = 0; j < 8; j++) {
        int id  = tid + j * 128;
        int arr = id >> 9;              // 0:Mthi 1:Mtlo
        int l   = id & 511;
        int row = l >> 2;
        int gr  = l & 3;
        uint32_t saddr = st + 16384 + arr * 8192 + sw32(row, gr);
        const __nv_bfloat16* g = (arr == 0 ? Mthi : Mtlo) +
            ((size_t)b * CC + row) * INNER + h * DH + g0 + gr * 8;
        cp16(saddr, g, true);
    }
}

__global__ __launch_bounds__(128, 2)
void final_mma_kernel(const __nv_bfloat16* __restrict__ Whi,
                      const __nv_bfloat16* __restrict__ Wlo,
                      const __nv_bfloat16* __restrict__ Mthi,
                      const __nv_bfloat16* __restrict__ Mtlo,
                      const float* __restrict__ bout,
                      float* __restrict__ out)
{
    extern __shared__ char smem[];           // 3 stages x 32KB

    const int pt = blockIdx.x;
    const int b  = pt >> 9;
    const int n0 = (pt & 511) * 128;

    const int tid  = threadIdx.x;            // 0..127
    const int wid  = tid >> 5;
    const int lane = tid & 31;
    const int grp  = lane >> 2;
    const int tid4 = lane & 3;
    const int wm   = wid & 1;                // 2 row-groups of 64
    const int wn   = wid >> 1;               // 2 col-groups of 64

    const int t8   = lane >> 3;
    const int r8   = lane & 7;
    const int a_roff = ((t8 & 1) << 3) + r8;
    const int a_gsel = t8 >> 1;
    const int b_roff = ((t8 >> 1) << 3) + r8;
    const int b_gsel = t8 & 1;

    float acc[4][8][4];
    #pragma unroll
    for (int i = 0; i < 4; i++)
        #pragma unroll
        for (int j = 0; j < 8; j++)
            #pragma unroll
            for (int r = 0; r < 4; r++) acc[i][j][r] = 0.f;

    uint32_t sbase = (uint32_t)__cvta_generic_to_shared(smem);

    fin_load(sbase, Whi, Wlo, Mthi, Mtlo, 0, b, n0, tid);
    asm volatile("cp.async.commit_group;\n" ::: "memory");
    fin_load(sbase + FSTAGE, Whi, Wlo, Mthi, Mtlo, 1, b, n0, tid);
    asm volatile("cp.async.commit_group;\n" ::: "memory");

    for (int it = 0; it < FNCHUNK; ++it) {
        const int cur = it % 3;
        if (it + 2 < FNCHUNK)
            fin_load(sbase + (uint32_t)((it + 2) % 3) * FSTAGE,
                     Whi, Wlo, Mthi, Mtlo, it + 2, b, n0, tid);
        asm volatile("cp.async.commit_group;\n" ::: "memory");
        asm volatile("cp.async.wait_group 2;\n" ::: "memory");
        __syncthreads();

        const uint32_t stA = sbase + (uint32_t)cur * FSTAGE;
        const uint32_t stB = stA + 16384;

        #pragma unroll
        for (int s = 0; s < 2; s++) {
            uint32_t ah[4][4], al[4][4];
            #pragma unroll
            for (int mi = 0; mi < 4; mi++) {
                int row = wm * 64 + mi * 16 + a_roff;
                int g = 2 * s + a_gsel;
                uint32_t addr = stA + sw32(row, g);
                ldsm4(ah[mi], addr);
                ldsm4(al[mi], addr + 8192);
            }
            #pragma unroll
            for (int np = 0; np < 4; np++) {
                int row = wn * 64 + np * 16 + b_roff;
                int g = 2 * s + b_gsel;
                uint32_t addr = stB + sw32(row, g);
                uint32_t bh[4], bl[4];
                ldsm4(bh, addr);
                ldsm4(bl, addr + 8192);
                #pragma unroll
                for (int mi = 0; mi < 4; mi++) {
                    mma_bf16(acc[mi][2 * np],     ah[mi][0], ah[mi][1], ah[mi][2], ah[mi][3], bh[0], bh[1]);
                    mma_bf16(acc[mi][2 * np + 1], ah[mi][0], ah[mi][1], ah[mi][2], ah[mi][3], bh[2], bh[3]);
                }
                #pragma unroll
                for (int mi = 0; mi < 4; mi++) {
                    mma_bf16(acc[mi][2 * np],     ah[mi][0], ah[mi][1], ah[mi][2], ah[mi][3], bl[0], bl[1]);
                    mma_bf16(acc[mi][2 * np + 1], ah[mi][0], ah[mi][1], ah[mi][2], ah[mi][3], bl[2], bl[3]);
                }
                #pragma unroll
                for (int mi = 0; mi < 4; mi++) {
                    mma_bf16(acc[mi][2 * np],     al[mi][0], al[mi][1], al[mi][2], al[mi][3], bh[0], bh[1]);
                    mma_bf16(acc[mi][2 * np + 1], al[mi][0], al[mi][1], al[mi][2], al[mi][3], bh[2], bh[3]);
                }
            }
        }
        __syncthreads();
    }

    #pragma unroll
    for (int mi = 0; mi < 4; mi++) {
        int row = wm * 64 + mi * 16 + grp;
        int n  = n0 + row;
        #pragma unroll
        for (int ni = 0; ni < 8; ni++) {
            int oc = wn * 64 + ni * 8 + tid4 * 2;
            float b0v = bout[oc], b1v = bout[oc + 1];
            size_t base0 = ((size_t)b * NN + n) * CC + oc;
            out[base0]     = acc[mi][ni][0] + b0v;
            out[base0 + 1] = acc[mi][ni][1] + b1v;
            size_t base1 = ((size_t)b * NN + n + 8) * CC + oc;
            out[base1]     = acc[mi][ni][2] + b0v;
            out[base1 + 1] = acc[mi][ni][3] + b1v;
        }
    }
}

// ---------------- launch ----------------
extern "C" void kernel_launch(void* const* d_in, const int* in_sizes, int n_in,
                              void* d_out, int out_size) {
    const float* x     = (const float*)d_in[0];
    const float* Wfx   = (const float*)d_in[1];
    const float* bfx   = (const float*)d_in[2];
    const float* Wx    = (const float*)d_in[3];
    const float* bx    = (const float*)d_in[4];
    const float* Wsl   = (const float*)d_in[5];
    const float* bsl   = (const float*)d_in[6];
    const float* temp  = (const float*)d_in[7];
    const float* Wq    = (const float*)d_in[8];
    const float* Wk    = (const float*)d_in[9];
    const float* Wv    = (const float*)d_in[10];
    const float* Wout  = (const float*)d_in[11];
    const float* bout  = (const float*)d_in[12];
    float* out = (float*)d_out;

    float *p_tokp, *p_normp, *p_tok, *p_norm, *p_lb;
    __nv_bfloat16 *p_xhi, *p_xlo, *p_whi, *p_wlo;
    __nv_bfloat16 *p_fxhi;
    __nv_bfloat16 *p_swhi, *p_swlo, *p_Mthi, *p_Mtlo;
    cudaGetSymbolAddress((void**)&p_tokp, g_tokp);
    cudaGetSymbolAddress((void**)&p_normp, g_normp);
    cudaGetSymbolAddress((void**)&p_tok, g_tok);
    cudaGetSymbolAddress((void**)&p_norm, g_norm);
    cudaGetSymbolAddress((void**)&p_lb, g_lbias);
    cudaGetSymbolAddress((void**)&p_xhi, g_xhi);
    cudaGetSymbolAddress((void**)&p_xlo, g_xlo);
    cudaGetSymbolAddress((void**)&p_whi, g_whi);
    cudaGetSymbolAddress((void**)&p_wlo, g_wlo);
    cudaGetSymbolAddress((void**)&p_fxhi, g_fxhi);
    cudaGetSymbolAddress((void**)&p_swhi, g_swhi);
    cudaGetSymbolAddress((void**)&p_swlo, g_swlo);
    cudaGetSymbolAddress((void**)&p_Mthi, g_Mthi);
    cudaGetSymbolAddress((void**)&p_Mtlo, g_Mtlo);

    static bool attr_set = false;
    if (!attr_set) {
        cudaFuncSetAttribute(conv_mma_kernel,
                             cudaFuncAttributeMaxDynamicSharedMemorySize, 3 * CSTAGE);
        cudaFuncSetAttribute(final_mma_kernel,
                             cudaFuncAttributeMaxDynamicSharedMemorySize, 3 * FSTAGE);
        attr_set = true;
    }

    dim3 blk(16, 16);

    // 0. staging (3 launches; conv is launch #4 for ncu visibility)
    split_x_kernel<<<(BB * NN * CC) / 1024, 256>>>(
        (const float4*)x, (uint2*)p_xhi, (uint2*)p_xlo);
    split_w_kernel<<<dim3(KTOT / 32, 512 / 32), dim3(32, 8)>>>(Wfx, p_whi, p_wlo);
    combine_w_kernel<<<dim3(HEADS, 10), 128>>>(Wx, Wsl, bx, bsl, temp, p_whi, p_wlo, p_lb);

    // 1. fused conv (launch #4): 128x128 tiles, 4 warps, 2 CTAs/SM, 3-stage
    conv_mma_kernel<<<dim3(8, 512, BB), 128, 3 * CSTAGE>>>(
        p_xhi, p_xlo, p_whi, p_wlo, bfx, p_lb, p_fxhi, p_swhi, p_swlo);

    // 2. slice token reduction on tensor cores + split reduce
    token_mma_kernel<<<dim3(SPLITS, BB * HEADS), 128>>>(
        p_swhi, p_swlo, p_fxhi, p_tokp, p_normp);
    split_reduce_kernel<<<260, 256>>>(p_tokp, p_normp, p_tok, p_norm);

    // 3. tiny attention + fused Wout fold -> Mt (bf16 hi/lo)
    attn_kernel<<<BB * HEADS, blk>>>(p_tok, p_norm, Wq, Wk, Wv, Wout, p_Mthi, p_Mtlo);

    // 4. fused scatter + projection: kc=32, 4 warps, 2 CTAs/SM, 3-stage
    final_mma_kernel<<<1024, 128, 3 * FSTAGE>>>(p_swhi, p_swlo, p_Mthi, p_Mtlo, bout, out);
}